// round 8
// baseline (speedup 1.0000x reference)
#include <cuda_runtime.h>
#include <cuda_fp16.h>
#include <math.h>
#include <stdint.h>

#define T_STEPS 200
#define BATCH   1024
#define XD      48
#define AD      15
#define IN_DIM  64
#define H_DIM   512
#define OUT_DIM 32
#define H1      513
#define KTOT    1152       // 2*64 (x hi|lo) + 2*512 (h hi|lo)
#define CHUNKS  18         // KTOT / 64
#define NCTA    128        // 32 nT x 4 mT, all co-resident (<=148 SMs)

// ---------------- static device scratch ----------------
__device__ __half g_Ax[T_STEPS][BATCH][128];   // [xhi|xlo] per step
__device__ __half g_Ah[2][BATCH][1024];        // [hhi|hlo] double buffered
__device__ __half g_W[2048][KTOT];             // permuted weights
__device__ float g_bias[2048];                 // permuted b_ih+b_hh
__device__ float g_hfinal[BATCH * H_DIM];
__device__ float g_z1[2][BATCH * H1];
__device__ float g_maxm;
__device__ unsigned g_count;                   // grid barrier counter

// ---------------- helpers ----------------
__device__ __forceinline__ uint32_t smem_u32(const void* p) {
    uint32_t a;
    asm("{ .reg .u64 t; cvta.to.shared.u64 t, %1; cvt.u32.u64 %0, t; }" : "=r"(a) : "l"(p));
    return a;
}
__device__ __forceinline__ uint32_t swz(uint32_t o) { return o ^ ((o >> 3) & 0x70); }
__device__ __forceinline__ void cpa16(uint32_t dst, const void* src) {
    asm volatile("cp.async.cg.shared.global [%0], [%1], 16;"
                 :: "r"(dst), "l"(__cvta_generic_to_global(src)));
}
__device__ __forceinline__ void ldsm4(uint32_t* r, uint32_t addr) {
    asm volatile("ldmatrix.sync.aligned.m8n8.x4.shared.b16 {%0,%1,%2,%3}, [%4];"
                 : "=r"(r[0]), "=r"(r[1]), "=r"(r[2]), "=r"(r[3]) : "r"(addr));
}
__device__ __forceinline__ void mma16816(float* d, const uint32_t* a, uint32_t b0, uint32_t b1) {
    asm volatile(
        "mma.sync.aligned.m16n8k16.row.col.f32.f16.f16.f32 "
        "{%0,%1,%2,%3},{%4,%5,%6,%7},{%8,%9},{%0,%1,%2,%3};"
        : "+f"(d[0]), "+f"(d[1]), "+f"(d[2]), "+f"(d[3])
        : "r"(a[0]), "r"(a[1]), "r"(a[2]), "r"(a[3]), "r"(b0), "r"(b1));
}

// ---------------- setup kernels ----------------
__global__ __launch_bounds__(256) void zero_kernel() {
    int idx = blockIdx.x * blockDim.x + threadIdx.x;
    int stride = gridDim.x * blockDim.x;
    __half z = __float2half(0.0f);
    for (int i = idx; i < BATCH * 1024; i += stride) (&g_Ah[0][0][0])[i] = z;
    if (idx == 0) g_count = 0;
}

__global__ __launch_bounds__(256) void maxm_kernel(const float* __restrict__ m) {
    __shared__ float red[256];
    float v = -1e30f;
    for (int i = threadIdx.x; i < T_STEPS * BATCH; i += 256) v = fmaxf(v, m[i]);
    red[threadIdx.x] = v;
    __syncthreads();
    for (int s = 128; s > 0; s >>= 1) {
        if (threadIdx.x < s) red[threadIdx.x] = fmaxf(red[threadIdx.x], red[threadIdx.x + s]);
        __syncthreads();
    }
    if (threadIdx.x == 0) g_maxm = red[0];
}

// Permuted weights: np = hb*64 + gate*16 + hc  <->  r = gate*512 + hb*16 + hc
// K layout: [Wih | Wih | Whh | Whh] (duplicated for the activation lo terms)
__global__ __launch_bounds__(256) void prep_w_kernel(
    const float* __restrict__ w_ih, const float* __restrict__ w_hh,
    const float* __restrict__ b_ih, const float* __restrict__ b_hh)
{
    int np = blockIdx.x;
    int hb = np >> 6;
    int gate = (np >> 4) & 3;
    int hc = np & 15;
    int r = gate * H_DIM + hb * 16 + hc;
    for (int k = threadIdx.x; k < KTOT; k += 256) {
        float v;
        if (k < 128)       v = w_ih[r * IN_DIM + (k & 63)];
        else               v = w_hh[r * H_DIM + ((k - 128) & 511)];
        g_W[np][k] = __float2half(v);
    }
    if (threadIdx.x == 0) g_bias[np] = b_ih[r] + b_hh[r];
}

__global__ __launch_bounds__(256) void prep_x_kernel(
    const float* __restrict__ x, const float* __restrict__ a)
{
    int s = blockIdx.x;
    int b = blockIdx.y * 4 + (threadIdx.x >> 6);
    int k = threadIdx.x & 63;
    int trow = T_STEPS - 1 - s;
    float v;
    if (k < XD)          v = x[((size_t)trow * BATCH + b) * XD + k];
    else if (k < 63)     v = a[((size_t)trow * BATCH + b) * AD + (k - XD)];
    else                 v = (float)s / g_maxm;
    __half hi = __float2half(v);
    __half lo = __float2half(v - __half2float(hi));
    g_Ax[s][b][k]      = hi;
    g_Ax[s][b][64 + k] = lo;
}

// ---------------- persistent LSTM kernel ----------------
// smem: B [18 chunks][64 rows][128B] = 147456; A buf0/buf1 32768 each.
#define SMEM_B     147456
#define ABUF_BYTES 32768
#define SMEM_REQ   (SMEM_B + 2 * ABUF_BYTES)

__global__ void __launch_bounds__(256, 1) lstm_persistent_kernel()
{
    extern __shared__ char sm[];
    uint32_t sb = smem_u32(sm);

    const int tid = threadIdx.x;
    const int wid = tid >> 5, lane = tid & 31;
    const int nT = blockIdx.x & 31;      // 32 N-tiles of 64 (16 hc x 4 gates)
    const int mT = blockIdx.x >> 5;      // 4 M-tiles of 256 batch rows

    // ---- prologue: B slice resident in smem ----
    {
        const __half* __restrict__ W = &g_W[nT * 64][0];
#pragma unroll
        for (int j = 0; j < CHUNKS; j++) {
#pragma unroll
            for (int i = 0; i < 2; i++) {
                int lin = i * 256 + tid;           // 512 x 16B per chunk
                int row = lin >> 3, c16 = lin & 7;
                cpa16(sb + j * 8192 + swz(row * 128 + c16 * 16),
                      W + (size_t)row * KTOT + j * 64 + c16 * 8);
            }
        }
        asm volatile("cp.async.commit_group;" ::: "memory");
        asm volatile("cp.async.wait_group 0;" ::: "memory");
        __syncthreads();
    }

    // bias: 4 gates x (p,t) for this lane's hc positions
    float bv[16];
#pragma unroll
    for (int g = 0; g < 4; g++)
#pragma unroll
        for (int p = 0; p < 2; p++)
#pragma unroll
            for (int t = 0; t < 2; t++)
                bv[g * 4 + p * 2 + t] = g_bias[nT * 64 + g * 16 + p * 8 + 2 * (lane & 3) + t];

    float cv[16];                        // cell state: registers for all 200 steps
#pragma unroll
    for (int e = 0; e < 16; e++) cv[e] = 0.0f;

    const uint32_t abuf0 = sb + SMEM_B;
    const int lrow = lane & 15;
    const uint32_t lcol = (lane >> 4) * 16;

    // issue A chunk j of step s into buffer j&1
    auto issue = [&](int s, int j) {
        uint32_t base = abuf0 + (j & 1) * ABUF_BYTES;
        const __half* src_base = (j < 2) ? &g_Ax[s][mT * 256][0] : &g_Ah[s & 1][mT * 256][0];
        int stride = (j < 2) ? 128 : 1024;
        int koff = (j < 2) ? j * 64 : (j - 2) * 64;
#pragma unroll
        for (int o = 0; o < 8; o++) {
            int lin = o * 256 + tid;               // 2048 x 16B
            int row = lin >> 3, c16 = lin & 7;
            cpa16(base + swz(row * 128 + c16 * 16),
                  src_base + (size_t)row * stride + koff + c16 * 8);
        }
        asm volatile("cp.async.commit_group;" ::: "memory");
    };

    issue(0, 0);                         // pre-issue first chunk of step 0

    for (int s = 0; s < T_STEPS; s++) {
        float acc[2][8][4];
#pragma unroll
        for (int mi = 0; mi < 2; mi++)
#pragma unroll
            for (int nb = 0; nb < 8; nb++)
#pragma unroll
                for (int q = 0; q < 4; q++) acc[mi][nb][q] = 0.0f;

        for (int j = 0; j < CHUNKS; j++) {
            if (j + 1 < CHUNKS) {
                issue(s, j + 1);
                asm volatile("cp.async.wait_group 1;" ::: "memory");
            } else {
                asm volatile("cp.async.wait_group 0;" ::: "memory");
            }
            __syncthreads();

            uint32_t Abase = abuf0 + (j & 1) * ABUF_BYTES;
            uint32_t Bbase = sb + j * 8192;
#pragma unroll
            for (int ks = 0; ks < 4; ks++) {
                uint32_t a0[4], a1[4];
                ldsm4(a0, Abase + swz((wid * 32 + lrow) * 128 + ks * 32 + lcol));
                ldsm4(a1, Abase + swz((wid * 32 + 16 + lrow) * 128 + ks * 32 + lcol));
#pragma unroll
                for (int nb4 = 0; nb4 < 4; nb4++) {
                    uint32_t b[4];
                    ldsm4(b, Bbase + swz((nb4 * 16 + lrow) * 128 + ks * 32 + lcol));
                    mma16816(acc[0][nb4 * 2 + 0], a0, b[0], b[2]);
                    mma16816(acc[0][nb4 * 2 + 1], a0, b[1], b[3]);
                    mma16816(acc[1][nb4 * 2 + 0], a1, b[0], b[2]);
                    mma16816(acc[1][nb4 * 2 + 1], a1, b[1], b[3]);
                }
            }
            __syncthreads();
        }

        // ---- epilogue: cell update in registers, h via smem transpose ----
        float* sH = (float*)(sm + SMEM_B + ABUF_BYTES);   // buf1: [256][17]
#pragma unroll
        for (int mi = 0; mi < 2; mi++) {
#pragma unroll
            for (int rh = 0; rh < 2; rh++) {
                int row = wid * 32 + mi * 16 + (lane >> 2) + rh * 8;
#pragma unroll
                for (int p = 0; p < 2; p++) {
#pragma unroll
                    for (int t = 0; t < 2; t++) {
                        int q = rh * 2 + t;
                        int e = ((mi * 2 + rh) * 2 + p) * 2 + t;
                        float iv = acc[mi][0 + p][q] + bv[0 + p * 2 + t];
                        float fv = acc[mi][2 + p][q] + bv[4 + p * 2 + t];
                        float gv = acc[mi][4 + p][q] + bv[8 + p * 2 + t];
                        float ov = acc[mi][6 + p][q] + bv[12 + p * 2 + t];
                        iv = 1.0f / (1.0f + expf(-iv));
                        fv = 1.0f / (1.0f + expf(-fv));
                        ov = 1.0f / (1.0f + expf(-ov));
                        gv = tanhf(gv);
                        float c = fv * cv[e] + iv * gv;
                        cv[e] = c;
                        sH[row * 17 + p * 8 + 2 * (lane & 3) + t] = ov * tanhf(c);
                    }
                }
            }
        }
        __syncthreads();

        // coalesced h write: one row per thread, 16 hc values
        {
            const int m = mT * 256 + tid;
            __half hi[16], lo[16];
            float hv[16];
#pragma unroll
            for (int i = 0; i < 16; i++) {
                hv[i] = sH[tid * 17 + i];
                __half h = __float2half(hv[i]);
                hi[i] = h;
                lo[i] = __float2half(hv[i] - __half2float(h));
            }
            __half* Aout = &g_Ah[(s + 1) & 1][0][0];
            size_t basei = (size_t)m * 1024 + nT * 16;
            uint4* vh = (uint4*)hi;
            uint4* vl = (uint4*)lo;
            ((uint4*)&Aout[basei])[0] = vh[0];       ((uint4*)&Aout[basei])[1] = vh[1];
            ((uint4*)&Aout[basei + 512])[0] = vl[0]; ((uint4*)&Aout[basei + 512])[1] = vl[1];
            if (s == T_STEPS - 1) {
                float4* pf = (float4*)&g_hfinal[(size_t)m * H_DIM + nT * 16];
#pragma unroll
                for (int q = 0; q < 4; q++) {
                    float4 t4;
                    t4.x = hv[q * 4]; t4.y = hv[q * 4 + 1];
                    t4.z = hv[q * 4 + 2]; t4.w = hv[q * 4 + 3];
                    pf[q] = t4;
                }
            }
        }
        __syncthreads();                 // sH reads done before buf1 reuse

        if (s + 1 < T_STEPS) {
            issue(s + 1, 0);             // x-only chunk: overlaps barrier latency
            __threadfence();
            // ---- grid barrier (monotonic counter; all 128 CTAs resident) ----
            __syncthreads();
            if (tid == 0) {
                atomicAdd(&g_count, 1u);
                unsigned target = (unsigned)(s + 1) * NCTA;
                unsigned v;
                do {
                    asm volatile("ld.acquire.gpu.u32 %0, [%1];"
                                 : "=r"(v) : "l"(&g_count));
                } while (v < target);
            }
            __syncthreads();
        }
    }
}

// ---------------- MLP heads ----------------
#define KCM 32
#define SIS 65
__global__ __launch_bounds__(256) void mlp1_kernel(
    const float* __restrict__ lw1, const float* __restrict__ lb1,
    const float* __restrict__ vw1, const float* __restrict__ vb1)
{
    __shared__ float sA[KCM * SIS];
    __shared__ float sW[KCM * SIS];
    const int head = blockIdx.z;
    const float* __restrict__ w  = head ? vw1 : lw1;
    const float* __restrict__ b1 = head ? vb1 : lb1;
    const float* __restrict__ A  = g_hfinal;
    float* __restrict__ z1 = g_z1[head];
    const int n0 = blockIdx.x * 64, b0 = blockIdx.y * 64;
    const int tid = threadIdx.x, tx = tid & 15, ty = tid >> 4;
    float acc[4][4];
#pragma unroll
    for (int i = 0; i < 4; i++)
#pragma unroll
        for (int j = 0; j < 4; j++) acc[i][j] = 0.0f;
    for (int k0 = 0; k0 < H_DIM; k0 += KCM) {
#pragma unroll
        for (int i = 0; i < 8; i++) {
            int lin = tid + i * 256;
            int kk = lin & 31, bb = lin >> 5;
            sA[kk * SIS + bb] = A[(b0 + bb) * H_DIM + k0 + kk];
        }
#pragma unroll
        for (int i = 0; i < 8; i++) {
            int lin = tid + i * 256;
            int kk = lin & 31, nn = lin >> 5;
            int n = n0 + nn;
            sW[kk * SIS + nn] = (n < H1) ? w[n * H_DIM + k0 + kk] : 0.0f;
        }
        __syncthreads();
#pragma unroll
        for (int k = 0; k < KCM; k++) {
            float rA[4], rW[4];
#pragma unroll
            for (int i = 0; i < 4; i++) rA[i] = sA[k * SIS + ty + 16 * i];
#pragma unroll
            for (int j = 0; j < 4; j++) rW[j] = sW[k * SIS + tx + 16 * j];
#pragma unroll
            for (int i = 0; i < 4; i++)
#pragma unroll
                for (int j = 0; j < 4; j++) acc[i][j] += rA[i] * rW[j];
        }
        __syncthreads();
    }
#pragma unroll
    for (int j = 0; j < 4; j++) {
        int n = n0 + tx + 16 * j;
        if (n < H1) {
            float bvv = b1[n];
#pragma unroll
            for (int i = 0; i < 4; i++)
                z1[(b0 + ty + 16 * i) * H1 + n] = tanhf(acc[i][j] + bvv);
        }
    }
}

__global__ __launch_bounds__(256) void mlp2_kernel(
    const float* __restrict__ lw2, const float* __restrict__ lb2,
    const float* __restrict__ vw2, const float* __restrict__ vb2,
    float* __restrict__ out)
{
    __shared__ float z1s[32 * 65];
    __shared__ float w2s[32 * 65];
    const int head = blockIdx.y;
    const float* __restrict__ w2 = head ? vw2 : lw2;
    const float* __restrict__ b2 = head ? vb2 : lb2;
    const float* __restrict__ z1 = g_z1[head];
    const int r0 = blockIdx.x * 32;
    const int tid = threadIdx.x, o = tid & 31, rg = tid >> 5;
    float acc[4] = {0.f, 0.f, 0.f, 0.f};
    for (int k0 = 0; k0 < H1; k0 += 64) {
#pragma unroll
        for (int i = 0; i < 8; i++) {
            int lin = tid + i * 256;
            int kk = lin & 63, rr = lin >> 6;
            int k = k0 + kk;
            z1s[rr * 65 + kk] = (k < H1) ? z1[(r0 + rr) * H1 + k] : 0.0f;
            w2s[rr * 65 + kk] = (k < H1) ? w2[rr * H1 + k] : 0.0f;
        }
        __syncthreads();
#pragma unroll
        for (int kk = 0; kk < 64; kk++) {
            float wv = w2s[o * 65 + kk];
#pragma unroll
            for (int r = 0; r < 4; r++) acc[r] += z1s[(rg * 4 + r) * 65 + kk] * wv;
        }
        __syncthreads();
    }
    float bvv = b2[o];
#pragma unroll
    for (int r = 0; r < 4; r++)
        out[(size_t)head * BATCH * OUT_DIM + (r0 + rg * 4 + r) * OUT_DIM + o] = tanhf(acc[r] + bvv);
}

// ---------------- launch ----------------
extern "C" void kernel_launch(void* const* d_in, const int* in_sizes, int n_in,
                              void* d_out, int out_size) {
    const float* x    = (const float*)d_in[0];
    const float* a    = (const float*)d_in[1];
    const float* m    = (const float*)d_in[2];
    const float* w_ih = (const float*)d_in[3];
    const float* w_hh = (const float*)d_in[4];
    const float* b_ih = (const float*)d_in[5];
    const float* b_hh = (const float*)d_in[6];
    const float* lw1  = (const float*)d_in[7];
    const float* lb1  = (const float*)d_in[8];
    const float* lw2  = (const float*)d_in[9];
    const float* lb2  = (const float*)d_in[10];
    const float* vw1  = (const float*)d_in[11];
    const float* vb1  = (const float*)d_in[12];
    const float* vw2  = (const float*)d_in[13];
    const float* vb2  = (const float*)d_in[14];

    cudaFuncSetAttribute(lstm_persistent_kernel,
                         cudaFuncAttributeMaxDynamicSharedMemorySize, SMEM_REQ);

    zero_kernel<<<512, 256>>>();
    maxm_kernel<<<1, 256>>>(m);
    prep_w_kernel<<<2048, 256>>>(w_ih, w_hh, b_ih, b_hh);
    prep_x_kernel<<<dim3(T_STEPS, BATCH / 4), 256>>>(x, a);

    lstm_persistent_kernel<<<NCTA, 256, SMEM_REQ>>>();

    mlp1_kernel<<<dim3(9, 16, 2), 256>>>(lw1, lb1, vw1, vb1);
    mlp2_kernel<<<dim3(32, 2), 256>>>(lw2, lb2, vw2, vb2, (float*)d_out);
}

// round 10
// speedup vs baseline: 1.3550x; 1.3550x over previous
#include <cuda_runtime.h>
#include <cuda_fp16.h>
#include <math.h>
#include <stdint.h>

#define T_STEPS 200
#define BATCH   1024
#define XD      48
#define AD      15
#define IN_DIM  64
#define H_DIM   512
#define OUT_DIM 32
#define H1      513
#define KTOT    1152       // 2*64 (x hi|lo) + 2*512 (h hi|lo)
#define CHUNKS  18         // KTOT / 64
#define NCTA    128        // 32 nT x 4 mT, all co-resident (<=148 SMs)

// ---------------- static device scratch ----------------
__device__ __half g_Ax[T_STEPS][BATCH][128];   // [xhi|xlo] per step
__device__ __half g_Ah[2][BATCH][1024];        // [hhi|hlo] double buffered
__device__ __half g_W[2048][KTOT];             // permuted weights
__device__ float g_bias[2048];                 // permuted b_ih+b_hh
__device__ float g_hfinal[BATCH * H_DIM];
__device__ float g_z1[2][BATCH * H1];
__device__ float g_maxm;
__device__ unsigned g_count;                   // grid barrier counter

// ---------------- helpers ----------------
__device__ __forceinline__ uint32_t smem_u32(const void* p) {
    uint32_t a;
    asm("{ .reg .u64 t; cvta.to.shared.u64 t, %1; cvt.u32.u64 %0, t; }" : "=r"(a) : "l"(p));
    return a;
}
__device__ __forceinline__ uint32_t swz(uint32_t o) { return o ^ ((o >> 3) & 0x70); }
__device__ __forceinline__ void cpa16(uint32_t dst, const void* src) {
    asm volatile("cp.async.cg.shared.global [%0], [%1], 16;"
                 :: "r"(dst), "l"(__cvta_generic_to_global(src)));
}
__device__ __forceinline__ void ldsm4(uint32_t* r, uint32_t addr) {
    asm volatile("ldmatrix.sync.aligned.m8n8.x4.shared.b16 {%0,%1,%2,%3}, [%4];"
                 : "=r"(r[0]), "=r"(r[1]), "=r"(r[2]), "=r"(r[3]) : "r"(addr));
}
__device__ __forceinline__ void mma16816(float* d, const uint32_t* a, uint32_t b0, uint32_t b1) {
    asm volatile(
        "mma.sync.aligned.m16n8k16.row.col.f32.f16.f16.f32 "
        "{%0,%1,%2,%3},{%4,%5,%6,%7},{%8,%9},{%0,%1,%2,%3};"
        : "+f"(d[0]), "+f"(d[1]), "+f"(d[2]), "+f"(d[3])
        : "r"(a[0]), "r"(a[1]), "r"(a[2]), "r"(a[3]), "r"(b0), "r"(b1));
}

// ---------------- setup kernels ----------------
__global__ __launch_bounds__(256) void zero_kernel() {
    int idx = blockIdx.x * blockDim.x + threadIdx.x;
    int stride = gridDim.x * blockDim.x;
    __half z = __float2half(0.0f);
    for (int i = idx; i < BATCH * 1024; i += stride) (&g_Ah[0][0][0])[i] = z;
    if (idx == 0) g_count = 0;
}

__global__ __launch_bounds__(256) void maxm_kernel(const float* __restrict__ m) {
    __shared__ float red[256];
    float v = -1e30f;
    for (int i = threadIdx.x; i < T_STEPS * BATCH; i += 256) v = fmaxf(v, m[i]);
    red[threadIdx.x] = v;
    __syncthreads();
    for (int s = 128; s > 0; s >>= 1) {
        if (threadIdx.x < s) red[threadIdx.x] = fmaxf(red[threadIdx.x], red[threadIdx.x + s]);
        __syncthreads();
    }
    if (threadIdx.x == 0) g_maxm = red[0];
}

// Permuted weights: np = hb*64 + gate*16 + hc  <->  r = gate*512 + hb*16 + hc
__global__ __launch_bounds__(256) void prep_w_kernel(
    const float* __restrict__ w_ih, const float* __restrict__ w_hh,
    const float* __restrict__ b_ih, const float* __restrict__ b_hh)
{
    int np = blockIdx.x;
    int hb = np >> 6;
    int gate = (np >> 4) & 3;
    int hc = np & 15;
    int r = gate * H_DIM + hb * 16 + hc;
    for (int k = threadIdx.x; k < KTOT; k += 256) {
        float v;
        if (k < 128)       v = w_ih[r * IN_DIM + (k & 63)];
        else               v = w_hh[r * H_DIM + ((k - 128) & 511)];
        g_W[np][k] = __float2half(v);
    }
    if (threadIdx.x == 0) g_bias[np] = b_ih[r] + b_hh[r];
}

__global__ __launch_bounds__(256) void prep_x_kernel(
    const float* __restrict__ x, const float* __restrict__ a)
{
    int s = blockIdx.x;
    int b = blockIdx.y * 4 + (threadIdx.x >> 6);
    int k = threadIdx.x & 63;
    int trow = T_STEPS - 1 - s;
    float v;
    if (k < XD)          v = x[((size_t)trow * BATCH + b) * XD + k];
    else if (k < 63)     v = a[((size_t)trow * BATCH + b) * AD + (k - XD)];
    else                 v = (float)s / g_maxm;
    __half hi = __float2half(v);
    __half lo = __float2half(v - __half2float(hi));
    g_Ax[s][b][k]      = hi;
    g_Ax[s][b][64 + k] = lo;
}

// ---------------- persistent LSTM kernel (barrier-free mainloop) ----------------
// smem: B [18][64 rows][128B] = 147456; A buf0/buf1 32768 each (warp-private slices);
//       sH DEDICATED region 256*17*4 = 17408 (warp-private rows, never aliased).
#define SMEM_B     147456
#define ABUF_BYTES 32768
#define SMEM_SH    (SMEM_B + 2 * ABUF_BYTES)
#define SMEM_REQ   (SMEM_SH + 256 * 17 * 4)    // 230400 <= 227KB limit

__global__ void __launch_bounds__(256, 1) lstm_persistent_kernel()
{
    extern __shared__ char sm[];
    uint32_t sb = smem_u32(sm);

    const int tid = threadIdx.x;
    const int wid = tid >> 5, lane = tid & 31;
    const int nT = blockIdx.x & 31;      // 32 N-tiles of 64 (16 hc x 4 gates)
    const int mT = blockIdx.x >> 5;      // 4 M-tiles of 256 batch rows

    // ---- prologue: B slice resident in smem ----
    {
        const __half* __restrict__ W = &g_W[nT * 64][0];
#pragma unroll
        for (int j = 0; j < CHUNKS; j++) {
#pragma unroll
            for (int i = 0; i < 2; i++) {
                int lin = i * 256 + tid;           // 512 x 16B per chunk
                int row = lin >> 3, c16 = lin & 7;
                cpa16(sb + j * 8192 + swz(row * 128 + c16 * 16),
                      W + (size_t)row * KTOT + j * 64 + c16 * 8);
            }
        }
        asm volatile("cp.async.commit_group;" ::: "memory");
        asm volatile("cp.async.wait_group 0;" ::: "memory");
        __syncthreads();
    }

    float bv[16];
#pragma unroll
    for (int g = 0; g < 4; g++)
#pragma unroll
        for (int p = 0; p < 2; p++)
#pragma unroll
            for (int t = 0; t < 2; t++)
                bv[g * 4 + p * 2 + t] = g_bias[nT * 64 + g * 16 + p * 8 + 2 * (lane & 3) + t];

    float cv[16];
#pragma unroll
    for (int e = 0; e < 16; e++) cv[e] = 0.0f;

    const uint32_t abuf0 = sb + SMEM_B;
    const int lrow = lane & 15;
    const uint32_t lcol = (lane >> 4) * 16;

    // warp-private A issue: warp w stages ONLY its rows [32w, 32w+32)
    auto issueW = [&](int s, int j) {
        uint32_t base = abuf0 + (j & 1) * ABUF_BYTES;
        const __half* src_base = (j < 2) ? &g_Ax[s][mT * 256][0] : &g_Ah[s & 1][mT * 256][0];
        int stride = (j < 2) ? 128 : 1024;
        int koff = (j < 2) ? j * 64 : (j - 2) * 64;
#pragma unroll
        for (int i = 0; i < 8; i++) {
            int lin = i * 32 + lane;               // 256 x 16B over 32 rows
            int row = wid * 32 + (lin >> 3), c16 = lin & 7;
            cpa16(base + swz(row * 128 + c16 * 16),
                  src_base + (size_t)row * stride + koff + c16 * 8);
        }
        asm volatile("cp.async.commit_group;" ::: "memory");
    };

    issueW(0, 0);                        // chunk 0 of step 0 in flight

    for (int s = 0; s < T_STEPS; s++) {
        float acc[2][8][4];
#pragma unroll
        for (int mi = 0; mi < 2; mi++)
#pragma unroll
            for (int nb = 0; nb < 8; nb++)
#pragma unroll
                for (int q = 0; q < 4; q++) acc[mi][nb][q] = 0.0f;

        // barrier-free chunk loop: each warp waits only on its own loads
        for (int j = 0; j < CHUNKS; j++) {
            if (j + 1 < CHUNKS) {
                issueW(s, j + 1);
                asm volatile("cp.async.wait_group 1;" ::: "memory");
            } else {
                asm volatile("cp.async.wait_group 0;" ::: "memory");
            }
            __syncwarp();

            uint32_t Abase = abuf0 + (j & 1) * ABUF_BYTES;
            uint32_t Bbase = sb + j * 8192;
#pragma unroll
            for (int ks = 0; ks < 4; ks++) {
                uint32_t a0[4], a1[4];
                ldsm4(a0, Abase + swz((wid * 32 + lrow) * 128 + ks * 32 + lcol));
                ldsm4(a1, Abase + swz((wid * 32 + 16 + lrow) * 128 + ks * 32 + lcol));
#pragma unroll
                for (int nb4 = 0; nb4 < 4; nb4++) {
                    uint32_t b[4];
                    ldsm4(b, Bbase + swz((nb4 * 16 + lrow) * 128 + ks * 32 + lcol));
                    mma16816(acc[0][nb4 * 2 + 0], a0, b[0], b[2]);
                    mma16816(acc[0][nb4 * 2 + 1], a0, b[1], b[3]);
                    mma16816(acc[1][nb4 * 2 + 0], a1, b[0], b[2]);
                    mma16816(acc[1][nb4 * 2 + 1], a1, b[1], b[3]);
                }
            }
        }

        // pre-issue next step's x chunk 0 into buf0 (warp-private rows; buf0 idle)
        if (s + 1 < T_STEPS) issueW(s + 1, 0);

        // ---- epilogue (warp-private): cell update, h via DEDICATED sH region ----
        float* sH = (float*)(sm + SMEM_SH);      // [256][17], rows warp-private, no alias
#pragma unroll
        for (int mi = 0; mi < 2; mi++) {
#pragma unroll
            for (int rh = 0; rh < 2; rh++) {
                int row = wid * 32 + mi * 16 + (lane >> 2) + rh * 8;
#pragma unroll
                for (int p = 0; p < 2; p++) {
#pragma unroll
                    for (int t = 0; t < 2; t++) {
                        int q = rh * 2 + t;
                        int e = ((mi * 2 + rh) * 2 + p) * 2 + t;
                        float iv = acc[mi][0 + p][q] + bv[0 + p * 2 + t];
                        float fv = acc[mi][2 + p][q] + bv[4 + p * 2 + t];
                        float gv = acc[mi][4 + p][q] + bv[8 + p * 2 + t];
                        float ov = acc[mi][6 + p][q] + bv[12 + p * 2 + t];
                        iv = __fdividef(1.0f, 1.0f + __expf(-iv));
                        fv = __fdividef(1.0f, 1.0f + __expf(-fv));
                        ov = __fdividef(1.0f, 1.0f + __expf(-ov));
                        gv = tanhf(gv);
                        float c = fv * cv[e] + iv * gv;
                        cv[e] = c;
                        sH[row * 17 + p * 8 + 2 * (lane & 3) + t] = ov * tanhf(c);
                    }
                }
            }
        }
        __syncwarp();

        // coalesced h write: thread tid handles row tid (warp-private in sH)
        {
            const int m = mT * 256 + tid;
            __half hi[16], lo[16];
            float hv[16];
#pragma unroll
            for (int i = 0; i < 16; i++) {
                hv[i] = sH[tid * 17 + i];
                __half h = __float2half(hv[i]);
                hi[i] = h;
                lo[i] = __float2half(hv[i] - __half2float(h));
            }
            __half* Aout = &g_Ah[(s + 1) & 1][0][0];
            size_t basei = (size_t)m * 1024 + nT * 16;
            uint4* vh = (uint4*)hi;
            uint4* vl = (uint4*)lo;
            ((uint4*)&Aout[basei])[0] = vh[0];       ((uint4*)&Aout[basei])[1] = vh[1];
            ((uint4*)&Aout[basei + 512])[0] = vl[0]; ((uint4*)&Aout[basei + 512])[1] = vl[1];
            if (s == T_STEPS - 1) {
                float4* pf = (float4*)&g_hfinal[(size_t)m * H_DIM + nT * 16];
#pragma unroll
                for (int q = 0; q < 4; q++) {
                    float4 t4;
                    t4.x = hv[q * 4]; t4.y = hv[q * 4 + 1];
                    t4.z = hv[q * 4 + 2]; t4.w = hv[q * 4 + 3];
                    pf[q] = t4;
                }
            }
        }

        if (s + 1 < T_STEPS) {
            // ---- grid barrier (only CTA-wide sync of the step) ----
            __threadfence();             // all threads: release h-writes to gpu scope
            __syncthreads();
            if (tid == 0) {
                atomicAdd(&g_count, 1u);
                unsigned target = (unsigned)(s + 1) * NCTA;
                unsigned v;
                do {
                    asm volatile("ld.acquire.gpu.u32 %0, [%1];"
                                 : "=r"(v) : "l"(&g_count));
                } while (v < target);
            }
            __syncthreads();
        }
    }
}

// ---------------- MLP heads ----------------
#define KCM 32
#define SIS 65
__global__ __launch_bounds__(256) void mlp1_kernel(
    const float* __restrict__ lw1, const float* __restrict__ lb1,
    const float* __restrict__ vw1, const float* __restrict__ vb1)
{
    __shared__ float sA[KCM * SIS];
    __shared__ float sW[KCM * SIS];
    const int head = blockIdx.z;
    const float* __restrict__ w  = head ? vw1 : lw1;
    const float* __restrict__ b1 = head ? vb1 : lb1;
    const float* __restrict__ A  = g_hfinal;
    float* __restrict__ z1 = g_z1[head];
    const int n0 = blockIdx.x * 64, b0 = blockIdx.y * 64;
    const int tid = threadIdx.x, tx = tid & 15, ty = tid >> 4;
    float acc[4][4];
#pragma unroll
    for (int i = 0; i < 4; i++)
#pragma unroll
        for (int j = 0; j < 4; j++) acc[i][j] = 0.0f;
    for (int k0 = 0; k0 < H_DIM; k0 += KCM) {
#pragma unroll
        for (int i = 0; i < 8; i++) {
            int lin = tid + i * 256;
            int kk = lin & 31, bb = lin >> 5;
            sA[kk * SIS + bb] = A[(b0 + bb) * H_DIM + k0 + kk];
        }
#pragma unroll
        for (int i = 0; i < 8; i++) {
            int lin = tid + i * 256;
            int kk = lin & 31, nn = lin >> 5;
            int n = n0 + nn;
            sW[kk * SIS + nn] = (n < H1) ? w[n * H_DIM + k0 + kk] : 0.0f;
        }
        __syncthreads();
#pragma unroll
        for (int k = 0; k < KCM; k++) {
            float rA[4], rW[4];
#pragma unroll
            for (int i = 0; i < 4; i++) rA[i] = sA[k * SIS + ty + 16 * i];
#pragma unroll
            for (int j = 0; j < 4; j++) rW[j] = sW[k * SIS + tx + 16 * j];
#pragma unroll
            for (int i = 0; i < 4; i++)
#pragma unroll
                for (int j = 0; j < 4; j++) acc[i][j] += rA[i] * rW[j];
        }
        __syncthreads();
    }
#pragma unroll
    for (int j = 0; j < 4; j++) {
        int n = n0 + tx + 16 * j;
        if (n < H1) {
            float bvv = b1[n];
#pragma unroll
            for (int i = 0; i < 4; i++)
                z1[(b0 + ty + 16 * i) * H1 + n] = tanhf(acc[i][j] + bvv);
        }
    }
}

__global__ __launch_bounds__(256) void mlp2_kernel(
    const float* __restrict__ lw2, const float* __restrict__ lb2,
    const float* __restrict__ vw2, const float* __restrict__ vb2,
    float* __restrict__ out)
{
    __shared__ float z1s[32 * 65];
    __shared__ float w2s[32 * 65];
    const int head = blockIdx.y;
    const float* __restrict__ w2 = head ? vw2 : lw2;
    const float* __restrict__ b2 = head ? vb2 : lb2;
    const float* __restrict__ z1 = g_z1[head];
    const int r0 = blockIdx.x * 32;
    const int tid = threadIdx.x, o = tid & 31, rg = tid >> 5;
    float acc[4] = {0.f, 0.f, 0.f, 0.f};
    for (int k0 = 0; k0 < H1; k0 += 64) {
#pragma unroll
        for (int i = 0; i < 8; i++) {
            int lin = tid + i * 256;
            int kk = lin & 63, rr = lin >> 6;
            int k = k0 + kk;
            z1s[rr * 65 + kk] = (k < H1) ? z1[(r0 + rr) * H1 + k] : 0.0f;
            w2s[rr * 65 + kk] = (k < H1) ? w2[rr * H1 + k] : 0.0f;
        }
        __syncthreads();
#pragma unroll
        for (int kk = 0; kk < 64; kk++) {
            float wv = w2s[o * 65 + kk];
#pragma unroll
            for (int r = 0; r < 4; r++) acc[r] += z1s[(rg * 4 + r) * 65 + kk] * wv;
        }
        __syncthreads();
    }
    float bvv = b2[o];
#pragma unroll
    for (int r = 0; r < 4; r++)
        out[(size_t)head * BATCH * OUT_DIM + (r0 + rg * 4 + r) * OUT_DIM + o] = tanhf(acc[r] + bvv);
}

// ---------------- launch ----------------
extern "C" void kernel_launch(void* const* d_in, const int* in_sizes, int n_in,
                              void* d_out, int out_size) {
    const float* x    = (const float*)d_in[0];
    const float* a    = (const float*)d_in[1];
    const float* m    = (const float*)d_in[2];
    const float* w_ih = (const float*)d_in[3];
    const float* w_hh = (const float*)d_in[4];
    const float* b_ih = (const float*)d_in[5];
    const float* b_hh = (const float*)d_in[6];
    const float* lw1  = (const float*)d_in[7];
    const float* lb1  = (const float*)d_in[8];
    const float* lw2  = (const float*)d_in[9];
    const float* lb2  = (const float*)d_in[10];
    const float* vw1  = (const float*)d_in[11];
    const float* vb1  = (const float*)d_in[12];
    const float* vw2  = (const float*)d_in[13];
    const float* vb2  = (const float*)d_in[14];

    cudaFuncSetAttribute(lstm_persistent_kernel,
                         cudaFuncAttributeMaxDynamicSharedMemorySize, SMEM_REQ);

    zero_kernel<<<512, 256>>>();
    maxm_kernel<<<1, 256>>>(m);
    prep_w_kernel<<<2048, 256>>>(w_ih, w_hh, b_ih, b_hh);
    prep_x_kernel<<<dim3(T_STEPS, BATCH / 4), 256>>>(x, a);

    lstm_persistent_kernel<<<NCTA, 256, SMEM_REQ>>>();

    mlp1_kernel<<<dim3(9, 16, 2), 256>>>(lw1, lb1, vw1, vb1);
    mlp2_kernel<<<dim3(32, 2), 256>>>(lw2, lb2, vw2, vb2, (float*)d_out);
}

// round 11
// speedup vs baseline: 2.1040x; 1.5528x over previous
#include <cuda_runtime.h>
#include <cuda_fp16.h>
#include <math.h>
#include <stdint.h>

#define T_STEPS 200
#define BATCH   1024
#define XD      48
#define AD      15
#define IN_DIM  64
#define H_DIM   512
#define OUT_DIM 32
#define H1      513
#define KTOT    640        // 2*64 (x hi|lo) + 512 (h hi)
#define CHUNKS  10         // KTOT / 64
#define NCTA    128        // 32 nT x 4 mT, all co-resident (<=148 SMs)

// ---------------- static device scratch ----------------
__device__ __half g_Ax[T_STEPS][BATCH][128];   // [xhi|xlo] per step
__device__ __half g_Ah[2][BATCH][512];         // h hi only, double buffered
__device__ __half g_W[2048][KTOT];             // permuted weights
__device__ float g_bias[2048];                 // permuted b_ih+b_hh
__device__ float g_hfinal[BATCH * H_DIM];
__device__ float g_z1[2][BATCH * H1];
__device__ float g_maxm;
__device__ unsigned g_count;                   // grid barrier counter

// ---------------- helpers ----------------
__device__ __forceinline__ uint32_t smem_u32(const void* p) {
    uint32_t a;
    asm("{ .reg .u64 t; cvta.to.shared.u64 t, %1; cvt.u32.u64 %0, t; }" : "=r"(a) : "l"(p));
    return a;
}
__device__ __forceinline__ uint32_t swz(uint32_t o) { return o ^ ((o >> 3) & 0x70); }
__device__ __forceinline__ void cpa16(uint32_t dst, const void* src) {
    asm volatile("cp.async.cg.shared.global [%0], [%1], 16;"
                 :: "r"(dst), "l"(__cvta_generic_to_global(src)));
}
__device__ __forceinline__ void ldsm4(uint32_t* r, uint32_t addr) {
    asm volatile("ldmatrix.sync.aligned.m8n8.x4.shared.b16 {%0,%1,%2,%3}, [%4];"
                 : "=r"(r[0]), "=r"(r[1]), "=r"(r[2]), "=r"(r[3]) : "r"(addr));
}
__device__ __forceinline__ void mma16816(float* d, const uint32_t* a, uint32_t b0, uint32_t b1) {
    asm volatile(
        "mma.sync.aligned.m16n8k16.row.col.f32.f16.f16.f32 "
        "{%0,%1,%2,%3},{%4,%5,%6,%7},{%8,%9},{%0,%1,%2,%3};"
        : "+f"(d[0]), "+f"(d[1]), "+f"(d[2]), "+f"(d[3])
        : "r"(a[0]), "r"(a[1]), "r"(a[2]), "r"(a[3]), "r"(b0), "r"(b1));
}

// ---------------- setup kernels ----------------
__global__ __launch_bounds__(256) void zero_kernel() {
    int idx = blockIdx.x * blockDim.x + threadIdx.x;
    int stride = gridDim.x * blockDim.x;
    __half z = __float2half(0.0f);
    for (int i = idx; i < BATCH * 512; i += stride) (&g_Ah[0][0][0])[i] = z;
    if (idx == 0) g_count = 0;
}

__global__ __launch_bounds__(256) void maxm_kernel(const float* __restrict__ m) {
    __shared__ float red[256];
    float v = -1e30f;
    for (int i = threadIdx.x; i < T_STEPS * BATCH; i += 256) v = fmaxf(v, m[i]);
    red[threadIdx.x] = v;
    __syncthreads();
    for (int s = 128; s > 0; s >>= 1) {
        if (threadIdx.x < s) red[threadIdx.x] = fmaxf(red[threadIdx.x], red[threadIdx.x + s]);
        __syncthreads();
    }
    if (threadIdx.x == 0) g_maxm = red[0];
}

// Permuted weights: np = hb*64 + gate*16 + hc  <->  r = gate*512 + hb*16 + hc
// K layout: [Wih | Wih | Whh]  (Wih duplicated for the x-lo term)
__global__ __launch_bounds__(256) void prep_w_kernel(
    const float* __restrict__ w_ih, const float* __restrict__ w_hh,
    const float* __restrict__ b_ih, const float* __restrict__ b_hh)
{
    int np = blockIdx.x;
    int hb = np >> 6;
    int gate = (np >> 4) & 3;
    int hc = np & 15;
    int r = gate * H_DIM + hb * 16 + hc;
    for (int k = threadIdx.x; k < KTOT; k += 256) {
        float v;
        if (k < 128)       v = w_ih[r * IN_DIM + (k & 63)];
        else               v = w_hh[r * H_DIM + (k - 128)];
        g_W[np][k] = __float2half(v);
    }
    if (threadIdx.x == 0) g_bias[np] = b_ih[r] + b_hh[r];
}

__global__ __launch_bounds__(256) void prep_x_kernel(
    const float* __restrict__ x, const float* __restrict__ a)
{
    int s = blockIdx.x;
    int b = blockIdx.y * 4 + (threadIdx.x >> 6);
    int k = threadIdx.x & 63;
    int trow = T_STEPS - 1 - s;
    float v;
    if (k < XD)          v = x[((size_t)trow * BATCH + b) * XD + k];
    else if (k < 63)     v = a[((size_t)trow * BATCH + b) * AD + (k - XD)];
    else                 v = (float)s / g_maxm;
    __half hi = __float2half(v);
    __half lo = __float2half(v - __half2float(hi));
    g_Ax[s][b][k]      = hi;
    g_Ax[s][b][64 + k] = lo;
}

// ---------------- persistent LSTM kernel (barrier-free mainloop) ----------------
// smem: B [10][64 rows][128B] = 81920; A buf0/buf1 32768 each (warp-private slices);
//       sH dedicated 256*17*4 = 17408. Total 164864.
#define SMEM_B     81920
#define ABUF_BYTES 32768
#define SMEM_SH    (SMEM_B + 2 * ABUF_BYTES)
#define SMEM_REQ   (SMEM_SH + 256 * 17 * 4)

__global__ void __launch_bounds__(256, 1) lstm_persistent_kernel()
{
    extern __shared__ char sm[];
    uint32_t sb = smem_u32(sm);

    const int tid = threadIdx.x;
    const int wid = tid >> 5, lane = tid & 31;
    const int nT = blockIdx.x & 31;      // 32 N-tiles of 64 (16 hc x 4 gates)
    const int mT = blockIdx.x >> 5;      // 4 M-tiles of 256 batch rows

    // ---- prologue: B slice resident in smem ----
    {
        const __half* __restrict__ W = &g_W[nT * 64][0];
#pragma unroll
        for (int j = 0; j < CHUNKS; j++) {
#pragma unroll
            for (int i = 0; i < 2; i++) {
                int lin = i * 256 + tid;           // 512 x 16B per chunk
                int row = lin >> 3, c16 = lin & 7;
                cpa16(sb + j * 8192 + swz(row * 128 + c16 * 16),
                      W + (size_t)row * KTOT + j * 64 + c16 * 8);
            }
        }
        asm volatile("cp.async.commit_group;" ::: "memory");
        asm volatile("cp.async.wait_group 0;" ::: "memory");
        __syncthreads();
    }

    float bv[16];
#pragma unroll
    for (int g = 0; g < 4; g++)
#pragma unroll
        for (int p = 0; p < 2; p++)
#pragma unroll
            for (int t = 0; t < 2; t++)
                bv[g * 4 + p * 2 + t] = g_bias[nT * 64 + g * 16 + p * 8 + 2 * (lane & 3) + t];

    float cv[16];
#pragma unroll
    for (int e = 0; e < 16; e++) cv[e] = 0.0f;

    const uint32_t abuf0 = sb + SMEM_B;
    const int lrow = lane & 15;
    const uint32_t lcol = (lane >> 4) * 16;

    // warp-private A issue: warp w stages ONLY its rows [32w, 32w+32)
    auto issueW = [&](int s, int j) {
        uint32_t base = abuf0 + (j & 1) * ABUF_BYTES;
        const __half* src_base = (j < 2) ? &g_Ax[s][mT * 256][0] : &g_Ah[s & 1][mT * 256][0];
        int stride = (j < 2) ? 128 : 512;
        int koff = (j < 2) ? j * 64 : (j - 2) * 64;
#pragma unroll
        for (int i = 0; i < 8; i++) {
            int lin = i * 32 + lane;               // 256 x 16B over 32 rows
            int row = wid * 32 + (lin >> 3), c16 = lin & 7;
            cpa16(base + swz(row * 128 + c16 * 16),
                  src_base + (size_t)row * stride + koff + c16 * 8);
        }
        asm volatile("cp.async.commit_group;" ::: "memory");
    };

    issueW(0, 0);                        // chunk 0 of step 0 in flight

    for (int s = 0; s < T_STEPS; s++) {
        float acc[2][8][4];
#pragma unroll
        for (int mi = 0; mi < 2; mi++)
#pragma unroll
            for (int nb = 0; nb < 8; nb++)
#pragma unroll
                for (int q = 0; q < 4; q++) acc[mi][nb][q] = 0.0f;

        // barrier-free chunk loop: each warp waits only on its own loads
        for (int j = 0; j < CHUNKS; j++) {
            if (j + 1 < CHUNKS) {
                issueW(s, j + 1);
                asm volatile("cp.async.wait_group 1;" ::: "memory");
            } else {
                asm volatile("cp.async.wait_group 0;" ::: "memory");
            }
            __syncwarp();

            uint32_t Abase = abuf0 + (j & 1) * ABUF_BYTES;
            uint32_t Bbase = sb + j * 8192;
#pragma unroll
            for (int ks = 0; ks < 4; ks++) {
                uint32_t a0[4], a1[4];
                ldsm4(a0, Abase + swz((wid * 32 + lrow) * 128 + ks * 32 + lcol));
                ldsm4(a1, Abase + swz((wid * 32 + 16 + lrow) * 128 + ks * 32 + lcol));
#pragma unroll
                for (int nb4 = 0; nb4 < 4; nb4++) {
                    uint32_t b[4];
                    ldsm4(b, Bbase + swz((nb4 * 16 + lrow) * 128 + ks * 32 + lcol));
                    mma16816(acc[0][nb4 * 2 + 0], a0, b[0], b[2]);
                    mma16816(acc[0][nb4 * 2 + 1], a0, b[1], b[3]);
                    mma16816(acc[1][nb4 * 2 + 0], a1, b[0], b[2]);
                    mma16816(acc[1][nb4 * 2 + 1], a1, b[1], b[3]);
                }
            }
        }

        // pre-issue next step's x chunk 0 into buf0 (warp-private rows; buf0 idle)
        if (s + 1 < T_STEPS) issueW(s + 1, 0);

        // ---- epilogue (warp-private): cell update, h via dedicated sH region ----
        float* sH = (float*)(sm + SMEM_SH);      // [256][17], rows warp-private
#pragma unroll
        for (int mi = 0; mi < 2; mi++) {
#pragma unroll
            for (int rh = 0; rh < 2; rh++) {
                int row = wid * 32 + mi * 16 + (lane >> 2) + rh * 8;
#pragma unroll
                for (int p = 0; p < 2; p++) {
#pragma unroll
                    for (int t = 0; t < 2; t++) {
                        int q = rh * 2 + t;
                        int e = ((mi * 2 + rh) * 2 + p) * 2 + t;
                        float iv = acc[mi][0 + p][q] + bv[0 + p * 2 + t];
                        float fv = acc[mi][2 + p][q] + bv[4 + p * 2 + t];
                        float gv = acc[mi][4 + p][q] + bv[8 + p * 2 + t];
                        float ov = acc[mi][6 + p][q] + bv[12 + p * 2 + t];
                        iv = __fdividef(1.0f, 1.0f + __expf(-iv));
                        fv = __fdividef(1.0f, 1.0f + __expf(-fv));
                        ov = __fdividef(1.0f, 1.0f + __expf(-ov));
                        gv = tanhf(gv);
                        float c = fv * cv[e] + iv * gv;
                        cv[e] = c;
                        sH[row * 17 + p * 8 + 2 * (lane & 3) + t] = ov * tanhf(c);
                    }
                }
            }
        }
        __syncwarp();

        // coalesced h write: thread tid handles row tid (warp-private in sH)
        {
            const int m = mT * 256 + tid;
            __half hi[16];
            float hv[16];
#pragma unroll
            for (int i = 0; i < 16; i++) {
                hv[i] = sH[tid * 17 + i];
                hi[i] = __float2half(hv[i]);
            }
            __half* Aout = &g_Ah[(s + 1) & 1][0][0];
            size_t basei = (size_t)m * 512 + nT * 16;
            uint4* vh = (uint4*)hi;
            ((uint4*)&Aout[basei])[0] = vh[0];
            ((uint4*)&Aout[basei])[1] = vh[1];
            if (s == T_STEPS - 1) {
                float4* pf = (float4*)&g_hfinal[(size_t)m * H_DIM + nT * 16];
#pragma unroll
                for (int q = 0; q < 4; q++) {
                    float4 t4;
                    t4.x = hv[q * 4]; t4.y = hv[q * 4 + 1];
                    t4.z = hv[q * 4 + 2]; t4.w = hv[q * 4 + 3];
                    pf[q] = t4;
                }
            }
        }

        if (s + 1 < T_STEPS) {
            // ---- grid barrier (only CTA-wide sync of the step) ----
            __threadfence();
            __syncthreads();
            if (tid == 0) {
                atomicAdd(&g_count, 1u);
                unsigned target = (unsigned)(s + 1) * NCTA;
                unsigned v;
                do {
                    asm volatile("ld.acquire.gpu.u32 %0, [%1];"
                                 : "=r"(v) : "l"(&g_count));
                } while (v < target);
            }
            __syncthreads();
        }
    }
}

// ---------------- MLP heads ----------------
#define KCM 32
#define SIS 65
__global__ __launch_bounds__(256) void mlp1_kernel(
    const float* __restrict__ lw1, const float* __restrict__ lb1,
    const float* __restrict__ vw1, const float* __restrict__ vb1)
{
    __shared__ float sA[KCM * SIS];
    __shared__ float sW[KCM * SIS];
    const int head = blockIdx.z;
    const float* __restrict__ w  = head ? vw1 : lw1;
    const float* __restrict__ b1 = head ? vb1 : lb1;
    const float* __restrict__ A  = g_hfinal;
    float* __restrict__ z1 = g_z1[head];
    const int n0 = blockIdx.x * 64, b0 = blockIdx.y * 64;
    const int tid = threadIdx.x, tx = tid & 15, ty = tid >> 4;
    float acc[4][4];
#pragma unroll
    for (int i = 0; i < 4; i++)
#pragma unroll
        for (int j = 0; j < 4; j++) acc[i][j] = 0.0f;
    for (int k0 = 0; k0 < H_DIM; k0 += KCM) {
#pragma unroll
        for (int i = 0; i < 8; i++) {
            int lin = tid + i * 256;
            int kk = lin & 31, bb = lin >> 5;
            sA[kk * SIS + bb] = A[(b0 + bb) * H_DIM + k0 + kk];
        }
#pragma unroll
        for (int i = 0; i < 8; i++) {
            int lin = tid + i * 256;
            int kk = lin & 31, nn = lin >> 5;
            int n = n0 + nn;
            sW[kk * SIS + nn] = (n < H1) ? w[n * H_DIM + k0 + kk] : 0.0f;
        }
        __syncthreads();
#pragma unroll
        for (int k = 0; k < KCM; k++) {
            float rA[4], rW[4];
#pragma unroll
            for (int i = 0; i < 4; i++) rA[i] = sA[k * SIS + ty + 16 * i];
#pragma unroll
            for (int j = 0; j < 4; j++) rW[j] = sW[k * SIS + tx + 16 * j];
#pragma unroll
            for (int i = 0; i < 4; i++)
#pragma unroll
                for (int j = 0; j < 4; j++) acc[i][j] += rA[i] * rW[j];
        }
        __syncthreads();
    }
#pragma unroll
    for (int j = 0; j < 4; j++) {
        int n = n0 + tx + 16 * j;
        if (n < H1) {
            float bvv = b1[n];
#pragma unroll
            for (int i = 0; i < 4; i++)
                z1[(b0 + ty + 16 * i) * H1 + n] = tanhf(acc[i][j] + bvv);
        }
    }
}

__global__ __launch_bounds__(256) void mlp2_kernel(
    const float* __restrict__ lw2, const float* __restrict__ lb2,
    const float* __restrict__ vw2, const float* __restrict__ vb2,
    float* __restrict__ out)
{
    __shared__ float z1s[32 * 65];
    __shared__ float w2s[32 * 65];
    const int head = blockIdx.y;
    const float* __restrict__ w2 = head ? vw2 : lw2;
    const float* __restrict__ b2 = head ? vb2 : lb2;
    const float* __restrict__ z1 = g_z1[head];
    const int r0 = blockIdx.x * 32;
    const int tid = threadIdx.x, o = tid & 31, rg = tid >> 5;
    float acc[4] = {0.f, 0.f, 0.f, 0.f};
    for (int k0 = 0; k0 < H1; k0 += 64) {
#pragma unroll
        for (int i = 0; i < 8; i++) {
            int lin = tid + i * 256;
            int kk = lin & 63, rr = lin >> 6;
            int k = k0 + kk;
            z1s[rr * 65 + kk] = (k < H1) ? z1[(r0 + rr) * H1 + k] : 0.0f;
            w2s[rr * 65 + kk] = (k < H1) ? w2[rr * H1 + k] : 0.0f;
        }
        __syncthreads();
#pragma unroll
        for (int kk = 0; kk < 64; kk++) {
            float wv = w2s[o * 65 + kk];
#pragma unroll
            for (int r = 0; r < 4; r++) acc[r] += z1s[(rg * 4 + r) * 65 + kk] * wv;
        }
        __syncthreads();
    }
    float bvv = b2[o];
#pragma unroll
    for (int r = 0; r < 4; r++)
        out[(size_t)head * BATCH * OUT_DIM + (r0 + rg * 4 + r) * OUT_DIM + o] = tanhf(acc[r] + bvv);
}

// ---------------- launch ----------------
extern "C" void kernel_launch(void* const* d_in, const int* in_sizes, int n_in,
                              void* d_out, int out_size) {
    const float* x    = (const float*)d_in[0];
    const float* a    = (const float*)d_in[1];
    const float* m    = (const float*)d_in[2];
    const float* w_ih = (const float*)d_in[3];
    const float* w_hh = (const float*)d_in[4];
    const float* b_ih = (const float*)d_in[5];
    const float* b_hh = (const float*)d_in[6];
    const float* lw1  = (const float*)d_in[7];
    const float* lb1  = (const float*)d_in[8];
    const float* lw2  = (const float*)d_in[9];
    const float* lb2  = (const float*)d_in[10];
    const float* vw1  = (const float*)d_in[11];
    const float* vb1  = (const float*)d_in[12];
    const float* vw2  = (const float*)d_in[13];
    const float* vb2  = (const float*)d_in[14];

    cudaFuncSetAttribute(lstm_persistent_kernel,
                         cudaFuncAttributeMaxDynamicSharedMemorySize, SMEM_REQ);

    zero_kernel<<<512, 256>>>();
    maxm_kernel<<<1, 256>>>(m);
    prep_w_kernel<<<2048, 256>>>(w_ih, w_hh, b_ih, b_hh);
    prep_x_kernel<<<dim3(T_STEPS, BATCH / 4), 256>>>(x, a);

    lstm_persistent_kernel<<<NCTA, 256, SMEM_REQ>>>();

    mlp1_kernel<<<dim3(9, 16, 2), 256>>>(lw1, lb1, vw1, vb1);
    mlp2_kernel<<<dim3(32, 2), 256>>>(lw2, lb2, vw2, vb2, (float*)d_out);
}

// round 12
// speedup vs baseline: 2.1865x; 1.0392x over previous
#include <cuda_runtime.h>
#include <cuda_fp16.h>
#include <math.h>
#include <stdint.h>

#define T_STEPS 200
#define BATCH   1024
#define XD      48
#define AD      15
#define IN_DIM  64
#define H_DIM   512
#define OUT_DIM 32
#define H1      513
#define KTOT    640        // 2*64 (x hi|lo) + 512 (h hi)
#define CHUNKS  10         // KTOT / 64
#define NCTA    128        // 32 nT x 4 mT
#define MTGRP   32         // CTAs per mT barrier group

// ---------------- static device scratch ----------------
__device__ __half g_Ax[T_STEPS][BATCH][128];   // [xhi|xlo] per step
__device__ __half g_Ah[2][BATCH][512];         // h hi only, double buffered
__device__ __half g_W[2048][KTOT];             // permuted weights
__device__ float g_bias[2048];                 // permuted b_ih+b_hh
__device__ float g_hfinal[BATCH * H_DIM];
__device__ float g_z1[2][BATCH * H1];
__device__ float g_maxm;
__device__ unsigned g_count4[4 * 32];          // per-mT barrier counters, 128B apart

// ---------------- helpers ----------------
__device__ __forceinline__ uint32_t smem_u32(const void* p) {
    uint32_t a;
    asm("{ .reg .u64 t; cvta.to.shared.u64 t, %1; cvt.u32.u64 %0, t; }" : "=r"(a) : "l"(p));
    return a;
}
__device__ __forceinline__ uint32_t swz(uint32_t o) { return o ^ ((o >> 3) & 0x70); }
__device__ __forceinline__ void cpa16(uint32_t dst, const void* src) {
    asm volatile("cp.async.cg.shared.global [%0], [%1], 16;"
                 :: "r"(dst), "l"(__cvta_generic_to_global(src)));
}
__device__ __forceinline__ void ldsm4(uint32_t* r, uint32_t addr) {
    asm volatile("ldmatrix.sync.aligned.m8n8.x4.shared.b16 {%0,%1,%2,%3}, [%4];"
                 : "=r"(r[0]), "=r"(r[1]), "=r"(r[2]), "=r"(r[3]) : "r"(addr));
}
__device__ __forceinline__ void mma16816(float* d, const uint32_t* a, uint32_t b0, uint32_t b1) {
    asm volatile(
        "mma.sync.aligned.m16n8k16.row.col.f32.f16.f16.f32 "
        "{%0,%1,%2,%3},{%4,%5,%6,%7},{%8,%9},{%0,%1,%2,%3};"
        : "+f"(d[0]), "+f"(d[1]), "+f"(d[2]), "+f"(d[3])
        : "r"(a[0]), "r"(a[1]), "r"(a[2]), "r"(a[3]), "r"(b0), "r"(b1));
}
__device__ __forceinline__ float sgm(float x) {          // sigmoid via SFU exp
    return __fdividef(1.0f, 1.0f + __expf(-x));
}
__device__ __forceinline__ float tanh_fast(float x) {    // 2*sigmoid(2x)-1, same SFU path
    return 2.0f * __fdividef(1.0f, 1.0f + __expf(-2.0f * x)) - 1.0f;
}

// ---------------- setup kernels ----------------
__global__ __launch_bounds__(256) void zero_kernel() {
    int idx = blockIdx.x * blockDim.x + threadIdx.x;
    int stride = gridDim.x * blockDim.x;
    __half z = __float2half(0.0f);
    for (int i = idx; i < BATCH * 512; i += stride) (&g_Ah[0][0][0])[i] = z;
    if (idx < 4 * 32) g_count4[idx] = 0;
}

__global__ __launch_bounds__(256) void maxm_kernel(const float* __restrict__ m) {
    __shared__ float red[256];
    float v = -1e30f;
    for (int i = threadIdx.x; i < T_STEPS * BATCH; i += 256) v = fmaxf(v, m[i]);
    red[threadIdx.x] = v;
    __syncthreads();
    for (int s = 128; s > 0; s >>= 1) {
        if (threadIdx.x < s) red[threadIdx.x] = fmaxf(red[threadIdx.x], red[threadIdx.x + s]);
        __syncthreads();
    }
    if (threadIdx.x == 0) g_maxm = red[0];
}

// Permuted weights: np = hb*64 + gate*16 + hc  <->  r = gate*512 + hb*16 + hc
__global__ __launch_bounds__(256) void prep_w_kernel(
    const float* __restrict__ w_ih, const float* __restrict__ w_hh,
    const float* __restrict__ b_ih, const float* __restrict__ b_hh)
{
    int np = blockIdx.x;
    int hb = np >> 6;
    int gate = (np >> 4) & 3;
    int hc = np & 15;
    int r = gate * H_DIM + hb * 16 + hc;
    for (int k = threadIdx.x; k < KTOT; k += 256) {
        float v;
        if (k < 128)       v = w_ih[r * IN_DIM + (k & 63)];
        else               v = w_hh[r * H_DIM + (k - 128)];
        g_W[np][k] = __float2half(v);
    }
    if (threadIdx.x == 0) g_bias[np] = b_ih[r] + b_hh[r];
}

__global__ __launch_bounds__(256) void prep_x_kernel(
    const float* __restrict__ x, const float* __restrict__ a)
{
    int s = blockIdx.x;
    int b = blockIdx.y * 4 + (threadIdx.x >> 6);
    int k = threadIdx.x & 63;
    int trow = T_STEPS - 1 - s;
    float v;
    if (k < XD)          v = x[((size_t)trow * BATCH + b) * XD + k];
    else if (k < 63)     v = a[((size_t)trow * BATCH + b) * AD + (k - XD)];
    else                 v = (float)s / g_maxm;
    __half hi = __float2half(v);
    __half lo = __float2half(v - __half2float(hi));
    g_Ax[s][b][k]      = hi;
    g_Ax[s][b][64 + k] = lo;
}

// ---------------- persistent LSTM kernel ----------------
// smem: B [10][64][128B] = 81920; A bufs 3 x 32768 (warp-private slices);
//       sH dedicated 256*17*4 = 17408. Total 197632.
#define SMEM_B     81920
#define ABUF_BYTES 32768
#define NSTAGE_A   3
#define SMEM_SH    (SMEM_B + NSTAGE_A * ABUF_BYTES)
#define SMEM_REQ   (SMEM_SH + 256 * 17 * 4)

__global__ void __launch_bounds__(256, 1) lstm_persistent_kernel()
{
    extern __shared__ char sm[];
    uint32_t sb = smem_u32(sm);

    const int tid = threadIdx.x;
    const int wid = tid >> 5, lane = tid & 31;
    const int nT = blockIdx.x & 31;      // 32 N-tiles of 64 (16 hc x 4 gates)
    const int mT = blockIdx.x >> 5;      // 4 M-tiles of 256 batch rows

    // ---- prologue: B slice resident in smem ----
    {
        const __half* __restrict__ W = &g_W[nT * 64][0];
#pragma unroll
        for (int j = 0; j < CHUNKS; j++) {
#pragma unroll
            for (int i = 0; i < 2; i++) {
                int lin = i * 256 + tid;           // 512 x 16B per chunk
                int row = lin >> 3, c16 = lin & 7;
                cpa16(sb + j * 8192 + swz(row * 128 + c16 * 16),
                      W + (size_t)row * KTOT + j * 64 + c16 * 8);
            }
        }
        asm volatile("cp.async.commit_group;" ::: "memory");
        asm volatile("cp.async.wait_group 0;" ::: "memory");
        __syncthreads();
    }

    float bv[16];
#pragma unroll
    for (int g = 0; g < 4; g++)
#pragma unroll
        for (int p = 0; p < 2; p++)
#pragma unroll
            for (int t = 0; t < 2; t++)
                bv[g * 4 + p * 2 + t] = g_bias[nT * 64 + g * 16 + p * 8 + 2 * (lane & 3) + t];

    float cv[16];
#pragma unroll
    for (int e = 0; e < 16; e++) cv[e] = 0.0f;

    const uint32_t abuf0 = sb + SMEM_B;
    const int lrow = lane & 15;
    const uint32_t lcol = (lane >> 4) * 16;
    unsigned* __restrict__ bar = &g_count4[mT * 32];

    // warp-private A issue: warp w stages ONLY its rows [32w, 32w+32); buffer j%3
    auto issueW = [&](int s, int j) {
        uint32_t base = abuf0 + (j % NSTAGE_A) * ABUF_BYTES;
        const __half* src_base = (j < 2) ? &g_Ax[s][mT * 256][0] : &g_Ah[s & 1][mT * 256][0];
        int stride = (j < 2) ? 128 : 512;
        int koff = (j < 2) ? j * 64 : (j - 2) * 64;
#pragma unroll
        for (int i = 0; i < 8; i++) {
            int lin = i * 32 + lane;               // 256 x 16B over 32 rows
            int row = wid * 32 + (lin >> 3), c16 = lin & 7;
            cpa16(base + swz(row * 128 + c16 * 16),
                  src_base + (size_t)row * stride + koff + c16 * 8);
        }
        asm volatile("cp.async.commit_group;" ::: "memory");
    };

    issueW(0, 0);                        // both x chunks of step 0 in flight
    issueW(0, 1);

    for (int s = 0; s < T_STEPS; s++) {
        float acc[2][8][4];
#pragma unroll
        for (int mi = 0; mi < 2; mi++)
#pragma unroll
            for (int nb = 0; nb < 8; nb++)
#pragma unroll
                for (int q = 0; q < 4; q++) acc[mi][nb][q] = 0.0f;

        // barrier-free chunk loop: 2 chunks in flight, 3 warp-private buffers
        for (int j = 0; j < CHUNKS; j++) {
            if (j + 2 < CHUNKS) {
                issueW(s, j + 2);
                asm volatile("cp.async.wait_group 2;" ::: "memory");
            } else if (j + 1 < CHUNKS) {
                asm volatile("cp.async.wait_group 1;" ::: "memory");
            } else {
                asm volatile("cp.async.wait_group 0;" ::: "memory");
            }
            __syncwarp();

            uint32_t Abase = abuf0 + (j % NSTAGE_A) * ABUF_BYTES;
            uint32_t Bbase = sb + j * 8192;
#pragma unroll
            for (int ks = 0; ks < 4; ks++) {
                uint32_t a0[4], a1[4];
                ldsm4(a0, Abase + swz((wid * 32 + lrow) * 128 + ks * 32 + lcol));
                ldsm4(a1, Abase + swz((wid * 32 + 16 + lrow) * 128 + ks * 32 + lcol));
#pragma unroll
                for (int nb4 = 0; nb4 < 4; nb4++) {
                    uint32_t b[4];
                    ldsm4(b, Bbase + swz((nb4 * 16 + lrow) * 128 + ks * 32 + lcol));
                    mma16816(acc[0][nb4 * 2 + 0], a0, b[0], b[2]);
                    mma16816(acc[0][nb4 * 2 + 1], a0, b[1], b[3]);
                    mma16816(acc[1][nb4 * 2 + 0], a1, b[0], b[2]);
                    mma16816(acc[1][nb4 * 2 + 1], a1, b[1], b[3]);
                }
            }
        }

        // pre-issue BOTH x chunks of next step (h-independent, warp-private bufs 0,1)
        if (s + 1 < T_STEPS) { issueW(s + 1, 0); issueW(s + 1, 1); }

        // ---- epilogue (warp-private): cell update, h via dedicated sH region ----
        float* sH = (float*)(sm + SMEM_SH);      // [256][17], rows warp-private
#pragma unroll
        for (int mi = 0; mi < 2; mi++) {
#pragma unroll
            for (int rh = 0; rh < 2; rh++) {
                int row = wid * 32 + mi * 16 + (lane >> 2) + rh * 8;
#pragma unroll
                for (int p = 0; p < 2; p++) {
#pragma unroll
                    for (int t = 0; t < 2; t++) {
                        int q = rh * 2 + t;
                        int e = ((mi * 2 + rh) * 2 + p) * 2 + t;
                        float iv = acc[mi][0 + p][q] + bv[0 + p * 2 + t];
                        float fv = acc[mi][2 + p][q] + bv[4 + p * 2 + t];
                        float gv = acc[mi][4 + p][q] + bv[8 + p * 2 + t];
                        float ov = acc[mi][6 + p][q] + bv[12 + p * 2 + t];
                        iv = sgm(iv);
                        fv = sgm(fv);
                        ov = sgm(ov);
                        gv = tanh_fast(gv);
                        float c = fv * cv[e] + iv * gv;
                        cv[e] = c;
                        sH[row * 17 + p * 8 + 2 * (lane & 3) + t] = ov * tanh_fast(c);
                    }
                }
            }
        }
        __syncwarp();

        // coalesced h write: thread tid handles row tid (warp-private in sH)
        {
            const int m = mT * 256 + tid;
            __half hi[16];
            float hv[16];
#pragma unroll
            for (int i = 0; i < 16; i++) {
                hv[i] = sH[tid * 17 + i];
                hi[i] = __float2half(hv[i]);
            }
            __half* Aout = &g_Ah[(s + 1) & 1][0][0];
            size_t basei = (size_t)m * 512 + nT * 16;
            uint4* vh = (uint4*)hi;
            ((uint4*)&Aout[basei])[0] = vh[0];
            ((uint4*)&Aout[basei])[1] = vh[1];
            if (s == T_STEPS - 1) {
                float4* pf = (float4*)&g_hfinal[(size_t)m * H_DIM + nT * 16];
#pragma unroll
                for (int q = 0; q < 4; q++) {
                    float4 t4;
                    t4.x = hv[q * 4]; t4.y = hv[q * 4 + 1];
                    t4.z = hv[q * 4 + 2]; t4.w = hv[q * 4 + 3];
                    pf[q] = t4;
                }
            }
        }

        if (s + 1 < T_STEPS) {
            // ---- per-mT grid barrier: only the 32 CTAs sharing this mT ----
            __threadfence();
            __syncthreads();
            if (tid == 0) {
                atomicAdd(bar, 1u);
                unsigned target = (unsigned)(s + 1) * MTGRP;
                unsigned v;
                do {
                    asm volatile("ld.acquire.gpu.u32 %0, [%1];"
                                 : "=r"(v) : "l"(bar));
                } while (v < target);
            }
            __syncthreads();
        }
    }
}

// ---------------- MLP heads ----------------
#define KCM 32
#define SIS 65
__global__ __launch_bounds__(256) void mlp1_kernel(
    const float* __restrict__ lw1, const float* __restrict__ lb1,
    const float* __restrict__ vw1, const float* __restrict__ vb1)
{
    __shared__ float sA[KCM * SIS];
    __shared__ float sW[KCM * SIS];
    const int head = blockIdx.z;
    const float* __restrict__ w  = head ? vw1 : lw1;
    const float* __restrict__ b1 = head ? vb1 : lb1;
    const float* __restrict__ A  = g_hfinal;
    float* __restrict__ z1 = g_z1[head];
    const int n0 = blockIdx.x * 64, b0 = blockIdx.y * 64;
    const int tid = threadIdx.x, tx = tid & 15, ty = tid >> 4;
    float acc[4][4];
#pragma unroll
    for (int i = 0; i < 4; i++)
#pragma unroll
        for (int j = 0; j < 4; j++) acc[i][j] = 0.0f;
    for (int k0 = 0; k0 < H_DIM; k0 += KCM) {
#pragma unroll
        for (int i = 0; i < 8; i++) {
            int lin = tid + i * 256;
            int kk = lin & 31, bb = lin >> 5;
            sA[kk * SIS + bb] = A[(b0 + bb) * H_DIM + k0 + kk];
        }
#pragma unroll
        for (int i = 0; i < 8; i++) {
            int lin = tid + i * 256;
            int kk = lin & 31, nn = lin >> 5;
            int n = n0 + nn;
            sW[kk * SIS + nn] = (n < H1) ? w[n * H_DIM + k0 + kk] : 0.0f;
        }
        __syncthreads();
#pragma unroll
        for (int k = 0; k < KCM; k++) {
            float rA[4], rW[4];
#pragma unroll
            for (int i = 0; i < 4; i++) rA[i] = sA[k * SIS + ty + 16 * i];
#pragma unroll
            for (int j = 0; j < 4; j++) rW[j] = sW[k * SIS + tx + 16 * j];
#pragma unroll
            for (int i = 0; i < 4; i++)
#pragma unroll
                for (int j = 0; j < 4; j++) acc[i][j] += rA[i] * rW[j];
        }
        __syncthreads();
    }
#pragma unroll
    for (int j = 0; j < 4; j++) {
        int n = n0 + tx + 16 * j;
        if (n < H1) {
            float bvv = b1[n];
#pragma unroll
            for (int i = 0; i < 4; i++)
                z1[(b0 + ty + 16 * i) * H1 + n] = tanhf(acc[i][j] + bvv);
        }
    }
}

__global__ __launch_bounds__(256) void mlp2_kernel(
    const float* __restrict__ lw2, const float* __restrict__ lb2,
    const float* __restrict__ vw2, const float* __restrict__ vb2,
    float* __restrict__ out)
{
    __shared__ float z1s[32 * 65];
    __shared__ float w2s[32 * 65];
    const int head = blockIdx.y;
    const float* __restrict__ w2 = head ? vw2 : lw2;
    const float* __restrict__ b2 = head ? vb2 : lb2;
    const float* __restrict__ z1 = g_z1[head];
    const int r0 = blockIdx.x * 32;
    const int tid = threadIdx.x, o = tid & 31, rg = tid >> 5;
    float acc[4] = {0.f, 0.f, 0.f, 0.f};
    for (int k0 = 0; k0 < H1; k0 += 64) {
#pragma unroll
        for (int i = 0; i < 8; i++) {
            int lin = tid + i * 256;
            int kk = lin & 63, rr = lin >> 6;
            int k = k0 + kk;
            z1s[rr * 65 + kk] = (k < H1) ? z1[(r0 + rr) * H1 + k] : 0.0f;
            w2s[rr * 65 + kk] = (k < H1) ? w2[rr * H1 + k] : 0.0f;
        }
        __syncthreads();
#pragma unroll
        for (int kk = 0; kk < 64; kk++) {
            float wv = w2s[o * 65 + kk];
#pragma unroll
            for (int r = 0; r < 4; r++) acc[r] += z1s[(rg * 4 + r) * 65 + kk] * wv;
        }
        __syncthreads();
    }
    float bvv = b2[o];
#pragma unroll
    for (int r = 0; r < 4; r++)
        out[(size_t)head * BATCH * OUT_DIM + (r0 + rg * 4 + r) * OUT_DIM + o] = tanhf(acc[r] + bvv);
}

// ---------------- launch ----------------
extern "C" void kernel_launch(void* const* d_in, const int* in_sizes, int n_in,
                              void* d_out, int out_size) {
    const float* x    = (const float*)d_in[0];
    const float* a    = (const float*)d_in[1];
    const float* m    = (const float*)d_in[2];
    const float* w_ih = (const float*)d_in[3];
    const float* w_hh = (const float*)d_in[4];
    const float* b_ih = (const float*)d_in[5];
    const float* b_hh = (const float*)d_in[6];
    const float* lw1  = (const float*)d_in[7];
    const float* lb1  = (const float*)d_in[8];
    const float* lw2  = (const float*)d_in[9];
    const float* lb2  = (const float*)d_in[10];
    const float* vw1  = (const float*)d_in[11];
    const float* vb1  = (const float*)d_in[12];
    const float* vw2  = (const float*)d_in[13];
    const float* vb2  = (const float*)d_in[14];

    cudaFuncSetAttribute(lstm_persistent_kernel,
                         cudaFuncAttributeMaxDynamicSharedMemorySize, SMEM_REQ);

    zero_kernel<<<512, 256>>>();
    maxm_kernel<<<1, 256>>>(m);
    prep_w_kernel<<<2048, 256>>>(w_ih, w_hh, b_ih, b_hh);
    prep_x_kernel<<<dim3(T_STEPS, BATCH / 4), 256>>>(x, a);

    lstm_persistent_kernel<<<NCTA, 256, SMEM_REQ>>>();

    mlp1_kernel<<<dim3(9, 16, 2), 256>>>(lw1, lb1, vw1, vb1);
    mlp2_kernel<<<dim3(32, 2), 256>>>(lw2, lb2, vw2, vb2, (float*)d_out);
}

// round 13
// speedup vs baseline: 2.3686x; 1.0833x over previous
#include <cuda_runtime.h>
#include <cuda_fp16.h>
#include <math.h>
#include <stdint.h>

#define T_STEPS 200
#define BATCH   1024
#define XD      48
#define AD      15
#define IN_DIM  64
#define H_DIM   512
#define OUT_DIM 32
#define H1      513
#define KTOT    576        // 64 (x hi) + 512 (h hi) — no redundancy
#define CHUNKS  9          // KTOT / 64
#define NCTA    128        // 32 nT x 4 mT
#define MTGRP   32         // CTAs per mT barrier group

// ---------------- static device scratch ----------------
__device__ __half g_Ax[T_STEPS][BATCH][64];    // x hi per step
__device__ __half g_Ah[2][BATCH][512];         // h hi, double buffered
__device__ __half g_W[2048][KTOT];             // permuted weights [Wih|Whh]
__device__ float g_bias[2048];                 // permuted b_ih+b_hh
__device__ float g_hfinal[BATCH * H_DIM];
__device__ float g_z1[2][BATCH * H1];
__device__ float g_maxm;
__device__ unsigned g_count4[4 * 32];          // per-mT barrier counters, 128B apart

// ---------------- helpers ----------------
__device__ __forceinline__ uint32_t smem_u32(const void* p) {
    uint32_t a;
    asm("{ .reg .u64 t; cvta.to.shared.u64 t, %1; cvt.u32.u64 %0, t; }" : "=r"(a) : "l"(p));
    return a;
}
__device__ __forceinline__ uint32_t swz(uint32_t o) { return o ^ ((o >> 3) & 0x70); }
__device__ __forceinline__ void cpa16(uint32_t dst, const void* src) {
    asm volatile("cp.async.cg.shared.global [%0], [%1], 16;"
                 :: "r"(dst), "l"(__cvta_generic_to_global(src)));
}
__device__ __forceinline__ void ldsm4(uint32_t* r, uint32_t addr) {
    asm volatile("ldmatrix.sync.aligned.m8n8.x4.shared.b16 {%0,%1,%2,%3}, [%4];"
                 : "=r"(r[0]), "=r"(r[1]), "=r"(r[2]), "=r"(r[3]) : "r"(addr));
}
__device__ __forceinline__ void mma16816(float* d, const uint32_t* a, uint32_t b0, uint32_t b1) {
    asm volatile(
        "mma.sync.aligned.m16n8k16.row.col.f32.f16.f16.f32 "
        "{%0,%1,%2,%3},{%4,%5,%6,%7},{%8,%9},{%0,%1,%2,%3};"
        : "+f"(d[0]), "+f"(d[1]), "+f"(d[2]), "+f"(d[3])
        : "r"(a[0]), "r"(a[1]), "r"(a[2]), "r"(a[3]), "r"(b0), "r"(b1));
}
__device__ __forceinline__ float sgm(float x) {
    return __fdividef(1.0f, 1.0f + __expf(-x));
}
__device__ __forceinline__ float tanh_fast(float x) {
    return 2.0f * __fdividef(1.0f, 1.0f + __expf(-2.0f * x)) - 1.0f;
}

// ---------------- setup kernels ----------------
__global__ __launch_bounds__(256) void zero_kernel() {
    int idx = blockIdx.x * blockDim.x + threadIdx.x;
    int stride = gridDim.x * blockDim.x;
    __half z = __float2half(0.0f);
    for (int i = idx; i < BATCH * 512; i += stride) (&g_Ah[0][0][0])[i] = z;
    if (idx < 4 * 32) g_count4[idx] = 0;
}

__global__ __launch_bounds__(256) void maxm_kernel(const float* __restrict__ m) {
    __shared__ float red[256];
    float v = -1e30f;
    for (int i = threadIdx.x; i < T_STEPS * BATCH; i += 256) v = fmaxf(v, m[i]);
    red[threadIdx.x] = v;
    __syncthreads();
    for (int s = 128; s > 0; s >>= 1) {
        if (threadIdx.x < s) red[threadIdx.x] = fmaxf(red[threadIdx.x], red[threadIdx.x + s]);
        __syncthreads();
    }
    if (threadIdx.x == 0) g_maxm = red[0];
}

// Permuted weights: np = hb*64 + gate*16 + hc  <->  r = gate*512 + hb*16 + hc
// K layout: [Wih (64) | Whh (512)]
__global__ __launch_bounds__(256) void prep_w_kernel(
    const float* __restrict__ w_ih, const float* __restrict__ w_hh,
    const float* __restrict__ b_ih, const float* __restrict__ b_hh)
{
    int np = blockIdx.x;
    int hb = np >> 6;
    int gate = (np >> 4) & 3;
    int hc = np & 15;
    int r = gate * H_DIM + hb * 16 + hc;
    for (int k = threadIdx.x; k < KTOT; k += 256) {
        float v;
        if (k < 64)        v = w_ih[r * IN_DIM + k];
        else               v = w_hh[r * H_DIM + (k - 64)];
        g_W[np][k] = __float2half(v);
    }
    if (threadIdx.x == 0) g_bias[np] = b_ih[r] + b_hh[r];
}

__global__ __launch_bounds__(256) void prep_x_kernel(
    const float* __restrict__ x, const float* __restrict__ a)
{
    int s = blockIdx.x;
    int b = blockIdx.y * 4 + (threadIdx.x >> 6);
    int k = threadIdx.x & 63;
    int trow = T_STEPS - 1 - s;
    float v;
    if (k < XD)          v = x[((size_t)trow * BATCH + b) * XD + k];
    else if (k < 63)     v = a[((size_t)trow * BATCH + b) * AD + (k - XD)];
    else                 v = (float)s / g_maxm;
    g_Ax[s][b][k] = __float2half(v);
}

// ---------------- persistent LSTM kernel ----------------
// smem: B [9][64][128B] = 73728; A bufs 3 x 32768; sH 256*17*4 = 17408.
#define SMEM_B     73728
#define ABUF_BYTES 32768
#define NSTAGE_A   3
#define SMEM_SH    (SMEM_B + NSTAGE_A * ABUF_BYTES)
#define SMEM_REQ   (SMEM_SH + 256 * 17 * 4)

__global__ void __launch_bounds__(256, 1) lstm_persistent_kernel()
{
    extern __shared__ char sm[];
    uint32_t sb = smem_u32(sm);

    const int tid = threadIdx.x;
    const int wid = tid >> 5, lane = tid & 31;
    const int nT = blockIdx.x & 31;      // 32 N-tiles of 64 (16 hc x 4 gates)
    const int mT = blockIdx.x >> 5;      // 4 M-tiles of 256 batch rows

    // ---- prologue: B slice resident in smem ----
    {
        const __half* __restrict__ W = &g_W[nT * 64][0];
#pragma unroll
        for (int j = 0; j < CHUNKS; j++) {
#pragma unroll
            for (int i = 0; i < 2; i++) {
                int lin = i * 256 + tid;           // 512 x 16B per chunk
                int row = lin >> 3, c16 = lin & 7;
                cpa16(sb + j * 8192 + swz(row * 128 + c16 * 16),
                      W + (size_t)row * KTOT + j * 64 + c16 * 8);
            }
        }
        asm volatile("cp.async.commit_group;" ::: "memory");
        asm volatile("cp.async.wait_group 0;" ::: "memory");
        __syncthreads();
    }

    float bv[16];
#pragma unroll
    for (int g = 0; g < 4; g++)
#pragma unroll
        for (int p = 0; p < 2; p++)
#pragma unroll
            for (int t = 0; t < 2; t++)
                bv[g * 4 + p * 2 + t] = g_bias[nT * 64 + g * 16 + p * 8 + 2 * (lane & 3) + t];

    float cv[16];
#pragma unroll
    for (int e = 0; e < 16; e++) cv[e] = 0.0f;

    const uint32_t abuf0 = sb + SMEM_B;
    const int lrow = lane & 15;
    const uint32_t lcol = (lane >> 4) * 16;
    unsigned* __restrict__ bar = &g_count4[mT * 32];

    // warp-private A issue: warp w stages ONLY its rows [32w, 32w+32); buffer j%3
    // chunk 0 = x (h-independent); chunks 1..8 = h
    auto issueW = [&](int s, int j) {
        uint32_t base = abuf0 + (j % NSTAGE_A) * ABUF_BYTES;
        const __half* src_base = (j < 1) ? &g_Ax[s][mT * 256][0] : &g_Ah[s & 1][mT * 256][0];
        int stride = (j < 1) ? 64 : 512;
        int koff = (j < 1) ? 0 : (j - 1) * 64;
#pragma unroll
        for (int i = 0; i < 8; i++) {
            int lin = i * 32 + lane;               // 256 x 16B over 32 rows
            int row = wid * 32 + (lin >> 3), c16 = lin & 7;
            cpa16(base + swz(row * 128 + c16 * 16),
                  src_base + (size_t)row * stride + koff + c16 * 8);
        }
        asm volatile("cp.async.commit_group;" ::: "memory");
    };

    issueW(0, 0);                        // x chunk of step 0 in flight

    for (int s = 0; s < T_STEPS; s++) {
        float acc[2][8][4];
#pragma unroll
        for (int mi = 0; mi < 2; mi++)
#pragma unroll
            for (int nb = 0; nb < 8; nb++)
#pragma unroll
                for (int q = 0; q < 4; q++) acc[mi][nb][q] = 0.0f;

        issueW(s, 1);                    // first h chunk (post-barrier)

        // barrier-free chunk loop: 2 chunks in flight, 3 warp-private buffers
        for (int j = 0; j < CHUNKS; j++) {
            if (j + 2 < CHUNKS) {
                issueW(s, j + 2);
                asm volatile("cp.async.wait_group 2;" ::: "memory");
            } else if (j + 1 < CHUNKS) {
                asm volatile("cp.async.wait_group 1;" ::: "memory");
            } else {
                asm volatile("cp.async.wait_group 0;" ::: "memory");
            }
            __syncwarp();

            uint32_t Abase = abuf0 + (j % NSTAGE_A) * ABUF_BYTES;
            uint32_t Bbase = sb + j * 8192;
#pragma unroll
            for (int ks = 0; ks < 4; ks++) {
                uint32_t a0[4], a1[4];
                ldsm4(a0, Abase + swz((wid * 32 + lrow) * 128 + ks * 32 + lcol));
                ldsm4(a1, Abase + swz((wid * 32 + 16 + lrow) * 128 + ks * 32 + lcol));
#pragma unroll
                for (int nb4 = 0; nb4 < 4; nb4++) {
                    uint32_t b[4];
                    ldsm4(b, Bbase + swz((nb4 * 16 + lrow) * 128 + ks * 32 + lcol));
                    mma16816(acc[0][nb4 * 2 + 0], a0, b[0], b[2]);
                    mma16816(acc[0][nb4 * 2 + 1], a0, b[1], b[3]);
                    mma16816(acc[1][nb4 * 2 + 0], a1, b[0], b[2]);
                    mma16816(acc[1][nb4 * 2 + 1], a1, b[1], b[3]);
                }
            }
        }

        // pre-issue next step's x chunk (h-independent, warp-private buf 0)
        if (s + 1 < T_STEPS) issueW(s + 1, 0);

        // ---- epilogue (warp-private): cell update, h via dedicated sH region ----
        float* sH = (float*)(sm + SMEM_SH);      // [256][17], rows warp-private
#pragma unroll
        for (int mi = 0; mi < 2; mi++) {
#pragma unroll
            for (int rh = 0; rh < 2; rh++) {
                int row = wid * 32 + mi * 16 + (lane >> 2) + rh * 8;
#pragma unroll
                for (int p = 0; p < 2; p++) {
#pragma unroll
                    for (int t = 0; t < 2; t++) {
                        int q = rh * 2 + t;
                        int e = ((mi * 2 + rh) * 2 + p) * 2 + t;
                        float iv = acc[mi][0 + p][q] + bv[0 + p * 2 + t];
                        float fv = acc[mi][2 + p][q] + bv[4 + p * 2 + t];
                        float gv = acc[mi][4 + p][q] + bv[8 + p * 2 + t];
                        float ov = acc[mi][6 + p][q] + bv[12 + p * 2 + t];
                        iv = sgm(iv);
                        fv = sgm(fv);
                        ov = sgm(ov);
                        gv = tanh_fast(gv);
                        float c = fv * cv[e] + iv * gv;
                        cv[e] = c;
                        sH[row * 17 + p * 8 + 2 * (lane & 3) + t] = ov * tanh_fast(c);
                    }
                }
            }
        }
        __syncwarp();

        // coalesced h write: thread tid handles row tid (warp-private in sH)
        {
            const int m = mT * 256 + tid;
            __half hi[16];
            float hv[16];
#pragma unroll
            for (int i = 0; i < 16; i++) {
                hv[i] = sH[tid * 17 + i];
                hi[i] = __float2half(hv[i]);
            }
            __half* Aout = &g_Ah[(s + 1) & 1][0][0];
            size_t basei = (size_t)m * 512 + nT * 16;
            uint4* vh = (uint4*)hi;
            ((uint4*)&Aout[basei])[0] = vh[0];
            ((uint4*)&Aout[basei])[1] = vh[1];
            if (s == T_STEPS - 1) {
                float4* pf = (float4*)&g_hfinal[(size_t)m * H_DIM + nT * 16];
#pragma unroll
                for (int q = 0; q < 4; q++) {
                    float4 t4;
                    t4.x = hv[q * 4]; t4.y = hv[q * 4 + 1];
                    t4.z = hv[q * 4 + 2]; t4.w = hv[q * 4 + 3];
                    pf[q] = t4;
                }
            }
        }

        if (s + 1 < T_STEPS) {
            // ---- per-mT grid barrier: only the 32 CTAs sharing this mT ----
            __threadfence();
            __syncthreads();
            if (tid == 0) {
                atomicAdd(bar, 1u);
                unsigned target = (unsigned)(s + 1) * MTGRP;
                unsigned v;
                do {
                    asm volatile("ld.acquire.gpu.u32 %0, [%1];"
                                 : "=r"(v) : "l"(bar));
                } while (v < target);
            }
            __syncthreads();
        }
    }
}

// ---------------- MLP heads ----------------
#define KCM 32
#define SIS 65
__global__ __launch_bounds__(256) void mlp1_kernel(
    const float* __restrict__ lw1, const float* __restrict__ lb1,
    const float* __restrict__ vw1, const float* __restrict__ vb1)
{
    __shared__ float sA[KCM * SIS];
    __shared__ float sW[KCM * SIS];
    const int head = blockIdx.z;
    const float* __restrict__ w  = head ? vw1 : lw1;
    const float* __restrict__ b1 = head ? vb1 : lb1;
    const float* __restrict__ A  = g_hfinal;
    float* __restrict__ z1 = g_z1[head];
    const int n0 = blockIdx.x * 64, b0 = blockIdx.y * 64;
    const int tid = threadIdx.x, tx = tid & 15, ty = tid >> 4;
    float acc[4][4];
#pragma unroll
    for (int i = 0; i < 4; i++)
#pragma unroll
        for (int j = 0; j < 4; j++) acc[i][j] = 0.0f;
    for (int k0 = 0; k0 < H_DIM; k0 += KCM) {
#pragma unroll
        for (int i = 0; i < 8; i++) {
            int lin = tid + i * 256;
            int kk = lin & 31, bb = lin >> 5;
            sA[kk * SIS + bb] = A[(b0 + bb) * H_DIM + k0 + kk];
        }
#pragma unroll
        for (int i = 0; i < 8; i++) {
            int lin = tid + i * 256;
            int kk = lin & 31, nn = lin >> 5;
            int n = n0 + nn;
            sW[kk * SIS + nn] = (n < H1) ? w[n * H_DIM + k0 + kk] : 0.0f;
        }
        __syncthreads();
#pragma unroll
        for (int k = 0; k < KCM; k++) {
            float rA[4], rW[4];
#pragma unroll
            for (int i = 0; i < 4; i++) rA[i] = sA[k * SIS + ty + 16 * i];
#pragma unroll
            for (int j = 0; j < 4; j++) rW[j] = sW[k * SIS + tx + 16 * j];
#pragma unroll
            for (int i = 0; i < 4; i++)
#pragma unroll
                for (int j = 0; j < 4; j++) acc[i][j] += rA[i] * rW[j];
        }
        __syncthreads();
    }
#pragma unroll
    for (int j = 0; j < 4; j++) {
        int n = n0 + tx + 16 * j;
        if (n < H1) {
            float bvv = b1[n];
#pragma unroll
            for (int i = 0; i < 4; i++)
                z1[(b0 + ty + 16 * i) * H1 + n] = tanhf(acc[i][j] + bvv);
        }
    }
}

__global__ __launch_bounds__(256) void mlp2_kernel(
    const float* __restrict__ lw2, const float* __restrict__ lb2,
    const float* __restrict__ vw2, const float* __restrict__ vb2,
    float* __restrict__ out)
{
    __shared__ float z1s[32 * 65];
    __shared__ float w2s[32 * 65];
    const int head = blockIdx.y;
    const float* __restrict__ w2 = head ? vw2 : lw2;
    const float* __restrict__ b2 = head ? vb2 : lb2;
    const float* __restrict__ z1 = g_z1[head];
    const int r0 = blockIdx.x * 32;
    const int tid = threadIdx.x, o = tid & 31, rg = tid >> 5;
    float acc[4] = {0.f, 0.f, 0.f, 0.f};
    for (int k0 = 0; k0 < H1; k0 += 64) {
#pragma unroll
        for (int i = 0; i < 8; i++) {
            int lin = tid + i * 256;
            int kk = lin & 63, rr = lin >> 6;
            int k = k0 + kk;
            z1s[rr * 65 + kk] = (k < H1) ? z1[(r0 + rr) * H1 + k] : 0.0f;
            w2s[rr * 65 + kk] = (k < H1) ? w2[rr * H1 + k] : 0.0f;
        }
        __syncthreads();
#pragma unroll
        for (int kk = 0; kk < 64; kk++) {
            float wv = w2s[o * 65 + kk];
#pragma unroll
            for (int r = 0; r < 4; r++) acc[r] += z1s[(rg * 4 + r) * 65 + kk] * wv;
        }
        __syncthreads();
    }
    float bvv = b2[o];
#pragma unroll
    for (int r = 0; r < 4; r++)
        out[(size_t)head * BATCH * OUT_DIM + (r0 + rg * 4 + r) * OUT_DIM + o] = tanhf(acc[r] + bvv);
}

// ---------------- launch ----------------
extern "C" void kernel_launch(void* const* d_in, const int* in_sizes, int n_in,
                              void* d_out, int out_size) {
    const float* x    = (const float*)d_in[0];
    const float* a    = (const float*)d_in[1];
    const float* m    = (const float*)d_in[2];
    const float* w_ih = (const float*)d_in[3];
    const float* w_hh = (const float*)d_in[4];
    const float* b_ih = (const float*)d_in[5];
    const float* b_hh = (const float*)d_in[6];
    const float* lw1  = (const float*)d_in[7];
    const float* lb1  = (const float*)d_in[8];
    const float* lw2  = (const float*)d_in[9];
    const float* lb2  = (const float*)d_in[10];
    const float* vw1  = (const float*)d_in[11];
    const float* vb1  = (const float*)d_in[12];
    const float* vw2  = (const float*)d_in[13];
    const float* vb2  = (const float*)d_in[14];

    cudaFuncSetAttribute(lstm_persistent_kernel,
                         cudaFuncAttributeMaxDynamicSharedMemorySize, SMEM_REQ);

    zero_kernel<<<512, 256>>>();
    maxm_kernel<<<1, 256>>>(m);
    prep_w_kernel<<<2048, 256>>>(w_ih, w_hh, b_ih, b_hh);
    prep_x_kernel<<<dim3(T_STEPS, BATCH / 4), 256>>>(x, a);

    lstm_persistent_kernel<<<NCTA, 256, SMEM_REQ>>>();

    mlp1_kernel<<<dim3(9, 16, 2), 256>>>(lw1, lb1, vw1, vb1);
    mlp2_kernel<<<dim3(32, 2), 256>>>(lw2, lb2, vw2, vb2, (float*)d_out);
}

// round 14
// speedup vs baseline: 2.3748x; 1.0026x over previous
#include <cuda_runtime.h>
#include <cuda_fp16.h>
#include <math.h>
#include <stdint.h>

#define T_STEPS 200
#define BATCH   1024
#define XD      48
#define AD      15
#define IN_DIM  64
#define H_DIM   512
#define OUT_DIM 32
#define H1      513
#define KTOT    576        // 64 (x hi) + 512 (h hi)
#define CHUNKS  9          // KTOT / 64
#define NCTA    128        // 32 nT x 4 mT
#define MTGRP   32         // CTAs per mT barrier group

// ---------------- static device scratch ----------------
__device__ __half g_Ax[T_STEPS][BATCH][64];    // x hi per step
__device__ __half g_Ah[2][BATCH][512];         // h hi, double buffered
__device__ __half g_W[2048][KTOT];             // permuted weights [Wih|Whh]
__device__ float g_bias[2048];                 // permuted b_ih+b_hh
__device__ float g_hfinal[BATCH * H_DIM];
__device__ float g_z1[2][BATCH * H1];
__device__ unsigned g_maxm_u;                  // max(m) as float bits (m > 0)
__device__ unsigned g_count4[4 * 32];          // per-mT barrier counters, 128B apart

// ---------------- helpers ----------------
__device__ __forceinline__ uint32_t smem_u32(const void* p) {
    uint32_t a;
    asm("{ .reg .u64 t; cvta.to.shared.u64 t, %1; cvt.u32.u64 %0, t; }" : "=r"(a) : "l"(p));
    return a;
}
__device__ __forceinline__ uint32_t swz(uint32_t o) { return o ^ ((o >> 3) & 0x70); }
__device__ __forceinline__ void cpa16(uint32_t dst, const void* src) {
    asm volatile("cp.async.cg.shared.global [%0], [%1], 16;"
                 :: "r"(dst), "l"(__cvta_generic_to_global(src)));
}
__device__ __forceinline__ void ldsm4(uint32_t* r, uint32_t addr) {
    asm volatile("ldmatrix.sync.aligned.m8n8.x4.shared.b16 {%0,%1,%2,%3}, [%4];"
                 : "=r"(r[0]), "=r"(r[1]), "=r"(r[2]), "=r"(r[3]) : "r"(addr));
}
__device__ __forceinline__ void mma16816(float* d, const uint32_t* a, uint32_t b0, uint32_t b1) {
    asm volatile(
        "mma.sync.aligned.m16n8k16.row.col.f32.f16.f16.f32 "
        "{%0,%1,%2,%3},{%4,%5,%6,%7},{%8,%9},{%0,%1,%2,%3};"
        : "+f"(d[0]), "+f"(d[1]), "+f"(d[2]), "+f"(d[3])
        : "r"(a[0]), "r"(a[1]), "r"(a[2]), "r"(a[3]), "r"(b0), "r"(b1));
}
__device__ __forceinline__ float sgm(float x) {
    return __fdividef(1.0f, 1.0f + __expf(-x));
}
__device__ __forceinline__ float tanh_fast(float x) {
    return 2.0f * __fdividef(1.0f, 1.0f + __expf(-2.0f * x)) - 1.0f;
}

// ---------------- setup kernels ----------------
__global__ __launch_bounds__(256) void zero_kernel() {
    int idx = blockIdx.x * blockDim.x + threadIdx.x;
    int stride = gridDim.x * blockDim.x;
    __half z = __float2half(0.0f);
    for (int i = idx; i < BATCH * 512; i += stride) (&g_Ah[0][0][0])[i] = z;
    if (idx < 4 * 32) g_count4[idx] = 0;
    if (idx == 4 * 32) g_maxm_u = 0u;
}

// parallel max over T*B (values > 0 -> float-bit atomicMax valid)
__global__ __launch_bounds__(256) void maxm_kernel(const float* __restrict__ m) {
    __shared__ float red[256];
    int base = blockIdx.x * 1024;
    float v = 0.0f;
#pragma unroll
    for (int i = 0; i < 4; i++) v = fmaxf(v, m[base + threadIdx.x + i * 256]);
    red[threadIdx.x] = v;
    __syncthreads();
    for (int s = 128; s > 0; s >>= 1) {
        if (threadIdx.x < s) red[threadIdx.x] = fmaxf(red[threadIdx.x], red[threadIdx.x + s]);
        __syncthreads();
    }
    if (threadIdx.x == 0) atomicMax(&g_maxm_u, __float_as_uint(red[0]));
}

// Permuted weights: np = hb*64 + gate*16 + hc  <->  r = gate*512 + hb*16 + hc
__global__ __launch_bounds__(256) void prep_w_kernel(
    const float* __restrict__ w_ih, const float* __restrict__ w_hh,
    const float* __restrict__ b_ih, const float* __restrict__ b_hh)
{
    int np = blockIdx.x;
    int hb = np >> 6;
    int gate = (np >> 4) & 3;
    int hc = np & 15;
    int r = gate * H_DIM + hb * 16 + hc;
    for (int k = threadIdx.x; k < KTOT; k += 256) {
        float v;
        if (k < 64)        v = w_ih[r * IN_DIM + k];
        else               v = w_hh[r * H_DIM + (k - 64)];
        g_W[np][k] = __float2half(v);
    }
    if (threadIdx.x == 0) g_bias[np] = b_ih[r] + b_hh[r];
}

// x hi per step; 16 elems/thread, vectorized stores. grid (200, 16), block 256.
__global__ __launch_bounds__(256) void prep_x_kernel(
    const float* __restrict__ x, const float* __restrict__ a)
{
    int s = blockIdx.x;
    int b = blockIdx.y * 64 + (threadIdx.x >> 2);
    int kb = (threadIdx.x & 3) * 16;
    int trow = T_STEPS - 1 - s;
    float tval = (float)s / __uint_as_float(g_maxm_u);
    const float* xr = x + ((size_t)trow * BATCH + b) * XD;
    const float* ar = a + ((size_t)trow * BATCH + b) * AD;
    __half h[16];
#pragma unroll
    for (int i = 0; i < 16; i++) {
        int k = kb + i;
        float v;
        if (k < XD)       v = xr[k];
        else if (k < 63)  v = ar[k - XD];
        else              v = tval;
        h[i] = __float2half(v);
    }
    uint4* dst = (uint4*)&g_Ax[s][b][kb];
    dst[0] = ((uint4*)h)[0];
    dst[1] = ((uint4*)h)[1];
}

// ---------------- persistent LSTM kernel: 512 threads, 16 warps ----------------
// smem: B [9][64][128B] = 73728; A bufs 3 x 32768; sH 256*17*4 = 17408.
#define SMEM_B     73728
#define ABUF_BYTES 32768
#define NSTAGE_A   3
#define SMEM_SH    (SMEM_B + NSTAGE_A * ABUF_BYTES)
#define SMEM_REQ   (SMEM_SH + 256 * 17 * 4)

__global__ void __launch_bounds__(512, 1) lstm_persistent_kernel()
{
    extern __shared__ char sm[];
    uint32_t sb = smem_u32(sm);

    const int tid = threadIdx.x;
    const int wid = tid >> 5, lane = tid & 31;
    const int nT = blockIdx.x & 31;      // 32 N-tiles of 64 (16 hc x 4 gates)
    const int mT = blockIdx.x >> 5;      // 4 M-tiles of 256 batch rows

    // ---- prologue: B slice resident in smem (512 ops/chunk, one per thread) ----
    {
        const __half* __restrict__ W = &g_W[nT * 64][0];
#pragma unroll
        for (int j = 0; j < CHUNKS; j++) {
            int row = tid >> 3, c16 = tid & 7;
            cpa16(sb + j * 8192 + swz(row * 128 + c16 * 16),
                  W + (size_t)row * KTOT + j * 64 + c16 * 8);
        }
        asm volatile("cp.async.commit_group;" ::: "memory");
        asm volatile("cp.async.wait_group 0;" ::: "memory");
        __syncthreads();
    }

    float bv[16];
#pragma unroll
    for (int g = 0; g < 4; g++)
#pragma unroll
        for (int p = 0; p < 2; p++)
#pragma unroll
            for (int t = 0; t < 2; t++)
                bv[g * 4 + p * 2 + t] = g_bias[nT * 64 + g * 16 + p * 8 + 2 * (lane & 3) + t];

    float cv[8];                         // 2 rows x 4 hc per thread
#pragma unroll
    for (int e = 0; e < 8; e++) cv[e] = 0.0f;

    const uint32_t abuf0 = sb + SMEM_B;
    const int lrow = lane & 15;
    const uint32_t lcol = (lane >> 4) * 16;
    unsigned* __restrict__ bar = &g_count4[mT * 32];

    // warp-private A issue: warp w stages its rows [16w, 16w+16); buffer j%3
    auto issueW = [&](int s, int j) {
        uint32_t base = abuf0 + (j % NSTAGE_A) * ABUF_BYTES;
        const __half* src_base = (j < 1) ? &g_Ax[s][mT * 256][0] : &g_Ah[s & 1][mT * 256][0];
        int stride = (j < 1) ? 64 : 512;
        int koff = (j < 1) ? 0 : (j - 1) * 64;
#pragma unroll
        for (int i = 0; i < 4; i++) {
            int lin = i * 32 + lane;               // 128 x 16B over 16 rows
            int row = wid * 16 + (lin >> 3), c16 = lin & 7;
            cpa16(base + swz(row * 128 + c16 * 16),
                  src_base + (size_t)row * stride + koff + c16 * 8);
        }
        asm volatile("cp.async.commit_group;" ::: "memory");
    };

    issueW(0, 0);                        // x chunk of step 0 in flight

    for (int s = 0; s < T_STEPS; s++) {
        float acc[8][4];
#pragma unroll
        for (int nb = 0; nb < 8; nb++)
#pragma unroll
            for (int q = 0; q < 4; q++) acc[nb][q] = 0.0f;

        issueW(s, 1);                    // first h chunk (post-barrier)

        for (int j = 0; j < CHUNKS; j++) {
            if (j + 2 < CHUNKS) {
                issueW(s, j + 2);
                asm volatile("cp.async.wait_group 2;" ::: "memory");
            } else if (j + 1 < CHUNKS) {
                asm volatile("cp.async.wait_group 1;" ::: "memory");
            } else {
                asm volatile("cp.async.wait_group 0;" ::: "memory");
            }
            __syncwarp();

            uint32_t Abase = abuf0 + (j % NSTAGE_A) * ABUF_BYTES;
            uint32_t Bbase = sb + j * 8192;
#pragma unroll
            for (int ks = 0; ks < 4; ks++) {
                uint32_t a0[4];
                ldsm4(a0, Abase + swz((wid * 16 + lrow) * 128 + ks * 32 + lcol));
#pragma unroll
                for (int nb4 = 0; nb4 < 4; nb4++) {
                    uint32_t b[4];
                    ldsm4(b, Bbase + swz((nb4 * 16 + lrow) * 128 + ks * 32 + lcol));
                    mma16816(acc[nb4 * 2 + 0], a0, b[0], b[2]);
                    mma16816(acc[nb4 * 2 + 1], a0, b[1], b[3]);
                }
            }
        }

        // pre-issue next step's x chunk (h-independent, warp-private buf 0)
        if (s + 1 < T_STEPS) issueW(s + 1, 0);

        // ---- epilogue (warp-private): cell update, h via dedicated sH region ----
        float* sH = (float*)(sm + SMEM_SH);      // [256][17], rows warp-private
#pragma unroll
        for (int rh = 0; rh < 2; rh++) {
            int row = wid * 16 + (lane >> 2) + rh * 8;
#pragma unroll
            for (int p = 0; p < 2; p++) {
#pragma unroll
                for (int t = 0; t < 2; t++) {
                    int q = rh * 2 + t;
                    int e = (rh * 2 + p) * 2 + t;
                    float iv = acc[0 + p][q] + bv[0 + p * 2 + t];
                    float fv = acc[2 + p][q] + bv[4 + p * 2 + t];
                    float gv = acc[4 + p][q] + bv[8 + p * 2 + t];
                    float ov = acc[6 + p][q] + bv[12 + p * 2 + t];
                    iv = sgm(iv);
                    fv = sgm(fv);
                    ov = sgm(ov);
                    gv = tanh_fast(gv);
                    float c = fv * cv[e] + iv * gv;
                    cv[e] = c;
                    sH[row * 17 + p * 8 + 2 * (lane & 3) + t] = ov * tanh_fast(c);
                }
            }
        }
        __syncwarp();

        // coalesced h write: thread handles half a row (8 hc)
        {
            const int r = tid >> 1, half = tid & 1;
            const int m = mT * 256 + r;
            __half hi[8];
            float hv[8];
#pragma unroll
            for (int i = 0; i < 8; i++) {
                hv[i] = sH[r * 17 + half * 8 + i];
                hi[i] = __float2half(hv[i]);
            }
            __half* Aout = &g_Ah[(s + 1) & 1][0][0];
            *((uint4*)&Aout[(size_t)m * 512 + nT * 16 + half * 8]) = ((uint4*)hi)[0];
            if (s == T_STEPS - 1) {
                float4* pf = (float4*)&g_hfinal[(size_t)m * H_DIM + nT * 16 + half * 8];
                float4 t4;
                t4.x = hv[0]; t4.y = hv[1]; t4.z = hv[2]; t4.w = hv[3];
                pf[0] = t4;
                t4.x = hv[4]; t4.y = hv[5]; t4.z = hv[6]; t4.w = hv[7];
                pf[1] = t4;
            }
        }

        if (s + 1 < T_STEPS) {
            // ---- per-mT grid barrier ----
            __threadfence();
            __syncthreads();
            if (tid == 0) {
                atomicAdd(bar, 1u);
                unsigned target = (unsigned)(s + 1) * MTGRP;
                unsigned v;
                do {
                    asm volatile("ld.acquire.gpu.u32 %0, [%1];"
                                 : "=r"(v) : "l"(bar));
                } while (v < target);
            }
            __syncthreads();
        }
    }
}

// ---------------- MLP heads ----------------
#define KCM 32
#define SIS 65
__global__ __launch_bounds__(256) void mlp1_kernel(
    const float* __restrict__ lw1, const float* __restrict__ lb1,
    const float* __restrict__ vw1, const float* __restrict__ vb1)
{
    __shared__ float sA[KCM * SIS];
    __shared__ float sW[KCM * SIS];
    const int head = blockIdx.z;
    const float* __restrict__ w  = head ? vw1 : lw1;
    const float* __restrict__ b1 = head ? vb1 : lb1;
    const float* __restrict__ A  = g_hfinal;
    float* __restrict__ z1 = g_z1[head];
    const int n0 = blockIdx.x * 64, b0 = blockIdx.y * 64;
    const int tid = threadIdx.x, tx = tid & 15, ty = tid >> 4;
    float acc[4][4];
#pragma unroll
    for (int i = 0; i < 4; i++)
#pragma unroll
        for (int j = 0; j < 4; j++) acc[i][j] = 0.0f;
    for (int k0 = 0; k0 < H_DIM; k0 += KCM) {
#pragma unroll
        for (int i = 0; i < 8; i++) {
            int lin = tid + i * 256;
            int kk = lin & 31, bb = lin >> 5;
            sA[kk * SIS + bb] = A[(b0 + bb) * H_DIM + k0 + kk];
        }
#pragma unroll
        for (int i = 0; i < 8; i++) {
            int lin = tid + i * 256;
            int kk = lin & 31, nn = lin >> 5;
            int n = n0 + nn;
            sW[kk * SIS + nn] = (n < H1) ? w[n * H_DIM + k0 + kk] : 0.0f;
        }
        __syncthreads();
#pragma unroll
        for (int k = 0; k < KCM; k++) {
            float rA[4], rW[4];
#pragma unroll
            for (int i = 0; i < 4; i++) rA[i] = sA[k * SIS + ty + 16 * i];
#pragma unroll
            for (int j = 0; j < 4; j++) rW[j] = sW[k * SIS + tx + 16 * j];
#pragma unroll
            for (int i = 0; i < 4; i++)
#pragma unroll
                for (int j = 0; j < 4; j++) acc[i][j] += rA[i] * rW[j];
        }
        __syncthreads();
    }
#pragma unroll
    for (int j = 0; j < 4; j++) {
        int n = n0 + tx + 16 * j;
        if (n < H1) {
            float bvv = b1[n];
#pragma unroll
            for (int i = 0; i < 4; i++)
                z1[(b0 + ty + 16 * i) * H1 + n] = tanhf(acc[i][j] + bvv);
        }
    }
}

__global__ __launch_bounds__(256) void mlp2_kernel(
    const float* __restrict__ lw2, const float* __restrict__ lb2,
    const float* __restrict__ vw2, const float* __restrict__ vb2,
    float* __restrict__ out)
{
    __shared__ float z1s[32 * 65];
    __shared__ float w2s[32 * 65];
    const int head = blockIdx.y;
    const float* __restrict__ w2 = head ? vw2 : lw2;
    const float* __restrict__ b2 = head ? vb2 : lb2;
    const float* __restrict__ z1 = g_z1[head];
    const int r0 = blockIdx.x * 32;
    const int tid = threadIdx.x, o = tid & 31, rg = tid >> 5;
    float acc[4] = {0.f, 0.f, 0.f, 0.f};
    for (int k0 = 0; k0 < H1; k0 += 64) {
#pragma unroll
        for (int i = 0; i < 8; i++) {
            int lin = tid + i * 256;
            int kk = lin & 63, rr = lin >> 6;
            int k = k0 + kk;
            z1s[rr * 65 + kk] = (k < H1) ? z1[(r0 + rr) * H1 + k] : 0.0f;
            w2s[rr * 65 + kk] = (k < H1) ? w2[rr * H1 + k] : 0.0f;
        }
        __syncthreads();
#pragma unroll
        for (int kk = 0; kk < 64; kk++) {
            float wv = w2s[o * 65 + kk];
#pragma unroll
            for (int r = 0; r < 4; r++) acc[r] += z1s[(rg * 4 + r) * 65 + kk] * wv;
        }
        __syncthreads();
    }
    float bvv = b2[o];
#pragma unroll
    for (int r = 0; r < 4; r++)
        out[(size_t)head * BATCH * OUT_DIM + (r0 + rg * 4 + r) * OUT_DIM + o] = tanhf(acc[r] + bvv);
}

// ---------------- launch ----------------
extern "C" void kernel_launch(void* const* d_in, const int* in_sizes, int n_in,
                              void* d_out, int out_size) {
    const float* x    = (const float*)d_in[0];
    const float* a    = (const float*)d_in[1];
    const float* m    = (const float*)d_in[2];
    const float* w_ih = (const float*)d_in[3];
    const float* w_hh = (const float*)d_in[4];
    const float* b_ih = (const float*)d_in[5];
    const float* b_hh = (const float*)d_in[6];
    const float* lw1  = (const float*)d_in[7];
    const float* lb1  = (const float*)d_in[8];
    const float* lw2  = (const float*)d_in[9];
    const float* lb2  = (const float*)d_in[10];
    const float* vw1  = (const float*)d_in[11];
    const float* vb1  = (const float*)d_in[12];
    const float* vw2  = (const float*)d_in[13];
    const float* vb2  = (const float*)d_in[14];

    cudaFuncSetAttribute(lstm_persistent_kernel,
                         cudaFuncAttributeMaxDynamicSharedMemorySize, SMEM_REQ);

    zero_kernel<<<512, 256>>>();
    maxm_kernel<<<200, 256>>>(m);
    prep_w_kernel<<<2048, 256>>>(w_ih, w_hh, b_ih, b_hh);
    prep_x_kernel<<<dim3(T_STEPS, 16), 256>>>(x, a);

    lstm_persistent_kernel<<<NCTA, 512, SMEM_REQ>>>();

    mlp1_kernel<<<dim3(9, 16, 2), 256>>>(lw1, lb1, vw1, vb1);
    mlp2_kernel<<<dim3(32, 2), 256>>>(lw2, lb2, vw2, vb2, (float*)d_out);
}

// round 15
// speedup vs baseline: 2.4314x; 1.0239x over previous
#include <cuda_runtime.h>
#include <cuda_fp16.h>
#include <math.h>
#include <stdint.h>

#define T_STEPS 200
#define BATCH   1024
#define XD      48
#define AD      15
#define IN_DIM  64
#define H_DIM   512
#define OUT_DIM 32
#define H1      513
#define KTOT    576        // 64 (x hi) + 512 (h hi)
#define CHUNKS  9          // KTOT / 64
#define NCTA    128        // 32 nT x 4 mT
#define MTGRP   32         // CTAs per mT barrier group

// ---------------- static device scratch ----------------
__device__ __half g_Ax[T_STEPS][BATCH][64];    // x hi per step
__device__ __half g_Ah[2][BATCH][512];         // h hi, double buffered
__device__ __half g_W[2048][KTOT];             // permuted LSTM weights [Wih|Whh]
__device__ __half g_W1[2][576][512];           // mlp1 weights fp16, zero-padded rows >=513
__device__ float g_bias[2048];                 // permuted b_ih+b_hh
__device__ float g_hfinal[BATCH * H_DIM];
__device__ float g_z1[2][BATCH * H1];
__device__ unsigned g_maxm_u;                  // max(m) as float bits (m > 0)
__device__ unsigned g_count4[4 * 32];          // per-mT barrier counters, 128B apart

// ---------------- helpers ----------------
__device__ __forceinline__ uint32_t smem_u32(const void* p) {
    uint32_t a;
    asm("{ .reg .u64 t; cvta.to.shared.u64 t, %1; cvt.u32.u64 %0, t; }" : "=r"(a) : "l"(p));
    return a;
}
__device__ __forceinline__ uint32_t swz(uint32_t o) { return o ^ ((o >> 3) & 0x70); }
__device__ __forceinline__ void cpa16(uint32_t dst, const void* src) {
    asm volatile("cp.async.cg.shared.global [%0], [%1], 16;"
                 :: "r"(dst), "l"(__cvta_generic_to_global(src)));
}
__device__ __forceinline__ void ldsm4(uint32_t* r, uint32_t addr) {
    asm volatile("ldmatrix.sync.aligned.m8n8.x4.shared.b16 {%0,%1,%2,%3}, [%4];"
                 : "=r"(r[0]), "=r"(r[1]), "=r"(r[2]), "=r"(r[3]) : "r"(addr));
}
__device__ __forceinline__ void mma16816(float* d, const uint32_t* a, uint32_t b0, uint32_t b1) {
    asm volatile(
        "mma.sync.aligned.m16n8k16.row.col.f32.f16.f16.f32 "
        "{%0,%1,%2,%3},{%4,%5,%6,%7},{%8,%9},{%0,%1,%2,%3};"
        : "+f"(d[0]), "+f"(d[1]), "+f"(d[2]), "+f"(d[3])
        : "r"(a[0]), "r"(a[1]), "r"(a[2]), "r"(a[3]), "r"(b0), "r"(b1));
}
__device__ __forceinline__ float sgm(float x) {
    return __fdividef(1.0f, 1.0f + __expf(-x));
}
__device__ __forceinline__ float tanh_fast(float x) {
    return 2.0f * __fdividef(1.0f, 1.0f + __expf(-2.0f * x)) - 1.0f;
}

// ---------------- setup kernels ----------------
__global__ __launch_bounds__(256) void zero_kernel() {
    int idx = blockIdx.x * blockDim.x + threadIdx.x;
    int stride = gridDim.x * blockDim.x;
    __half z = __float2half(0.0f);
    for (int i = idx; i < BATCH * 512; i += stride) (&g_Ah[0][0][0])[i] = z;
    if (idx < 4 * 32) g_count4[idx] = 0;
    if (idx == 4 * 32) g_maxm_u = 0u;
}

__global__ __launch_bounds__(256) void maxm_kernel(const float* __restrict__ m) {
    __shared__ float red[256];
    int base = blockIdx.x * 1024;
    float v = 0.0f;
#pragma unroll
    for (int i = 0; i < 4; i++) v = fmaxf(v, m[base + threadIdx.x + i * 256]);
    red[threadIdx.x] = v;
    __syncthreads();
    for (int s = 128; s > 0; s >>= 1) {
        if (threadIdx.x < s) red[threadIdx.x] = fmaxf(red[threadIdx.x], red[threadIdx.x + s]);
        __syncthreads();
    }
    if (threadIdx.x == 0) atomicMax(&g_maxm_u, __float_as_uint(red[0]));
}

// Permuted LSTM weights: np = hb*64 + gate*16 + hc  <->  r = gate*512 + hb*16 + hc
__global__ __launch_bounds__(256) void prep_w_kernel(
    const float* __restrict__ w_ih, const float* __restrict__ w_hh,
    const float* __restrict__ b_ih, const float* __restrict__ b_hh)
{
    int np = blockIdx.x;
    int hb = np >> 6;
    int gate = (np >> 4) & 3;
    int hc = np & 15;
    int r = gate * H_DIM + hb * 16 + hc;
    for (int k = threadIdx.x; k < KTOT; k += 256) {
        float v;
        if (k < 64)        v = w_ih[r * IN_DIM + k];
        else               v = w_hh[r * H_DIM + (k - 64)];
        g_W[np][k] = __float2half(v);
    }
    if (threadIdx.x == 0) g_bias[np] = b_ih[r] + b_hh[r];
}

// mlp1 weights fp16, padded to 576 rows. grid (576, 2)
__global__ __launch_bounds__(256) void prep_w1_kernel(
    const float* __restrict__ lw1, const float* __restrict__ vw1)
{
    int n = blockIdx.x;
    int head = blockIdx.y;
    const float* __restrict__ w = head ? vw1 : lw1;
    for (int k = threadIdx.x; k < H_DIM; k += 256)
        g_W1[head][n][k] = (n < H1) ? __float2half(w[n * H_DIM + k]) : __float2half(0.0f);
}

// x hi per step, vectorized float4 loads. grid (200, 16), block 256.
__global__ __launch_bounds__(256) void prep_x_kernel(
    const float* __restrict__ x, const float* __restrict__ a)
{
    int s = blockIdx.x;
    int b = blockIdx.y * 64 + (threadIdx.x >> 2);
    int kb = (threadIdx.x & 3) * 16;
    int trow = T_STEPS - 1 - s;
    __half h[16];
    if (kb < XD) {                        // kb = 0,16,32 : pure x, 16B-aligned
        const float4* xr = (const float4*)(x + ((size_t)trow * BATCH + b) * XD + kb);
        float4 v[4];
#pragma unroll
        for (int i = 0; i < 4; i++) v[i] = xr[i];
        const float* vf = (const float*)v;
#pragma unroll
        for (int i = 0; i < 16; i++) h[i] = __float2half(vf[i]);
    } else {                              // kb = 48 : whole a row + t
        const float* ar = a + ((size_t)trow * BATCH + b) * AD;
        float tval = (float)s / __uint_as_float(g_maxm_u);
#pragma unroll
        for (int i = 0; i < 15; i++) h[i] = __float2half(ar[i]);
        h[15] = __float2half(tval);
    }
    uint4* dst = (uint4*)&g_Ax[s][b][kb];
    dst[0] = ((uint4*)h)[0];
    dst[1] = ((uint4*)h)[1];
}

// ---------------- persistent LSTM kernel: 512 threads, 16 warps ----------------
#define SMEM_B     73728
#define ABUF_BYTES 32768
#define NSTAGE_A   3
#define SMEM_SH    (SMEM_B + NSTAGE_A * ABUF_BYTES)
#define SMEM_REQ   (SMEM_SH + 256 * 17 * 4)

__global__ void __launch_bounds__(512, 1) lstm_persistent_kernel()
{
    extern __shared__ char sm[];
    uint32_t sb = smem_u32(sm);

    const int tid = threadIdx.x;
    const int wid = tid >> 5, lane = tid & 31;
    const int nT = blockIdx.x & 31;      // 32 N-tiles of 64 (16 hc x 4 gates)
    const int mT = blockIdx.x >> 5;      // 4 M-tiles of 256 batch rows

    // ---- prologue: B slice resident in smem ----
    {
        const __half* __restrict__ W = &g_W[nT * 64][0];
#pragma unroll
        for (int j = 0; j < CHUNKS; j++) {
            int row = tid >> 3, c16 = tid & 7;
            cpa16(sb + j * 8192 + swz(row * 128 + c16 * 16),
                  W + (size_t)row * KTOT + j * 64 + c16 * 8);
        }
        asm volatile("cp.async.commit_group;" ::: "memory");
        asm volatile("cp.async.wait_group 0;" ::: "memory");
        __syncthreads();
    }

    float bv[16];
#pragma unroll
    for (int g = 0; g < 4; g++)
#pragma unroll
        for (int p = 0; p < 2; p++)
#pragma unroll
            for (int t = 0; t < 2; t++)
                bv[g * 4 + p * 2 + t] = g_bias[nT * 64 + g * 16 + p * 8 + 2 * (lane & 3) + t];

    float cv[8];
#pragma unroll
    for (int e = 0; e < 8; e++) cv[e] = 0.0f;

    const uint32_t abuf0 = sb + SMEM_B;
    const int lrow = lane & 15;
    const uint32_t lcol = (lane >> 4) * 16;
    unsigned* __restrict__ bar = &g_count4[mT * 32];

    auto issueW = [&](int s, int j) {
        uint32_t base = abuf0 + (j % NSTAGE_A) * ABUF_BYTES;
        const __half* src_base = (j < 1) ? &g_Ax[s][mT * 256][0] : &g_Ah[s & 1][mT * 256][0];
        int stride = (j < 1) ? 64 : 512;
        int koff = (j < 1) ? 0 : (j - 1) * 64;
#pragma unroll
        for (int i = 0; i < 4; i++) {
            int lin = i * 32 + lane;
            int row = wid * 16 + (lin >> 3), c16 = lin & 7;
            cpa16(base + swz(row * 128 + c16 * 16),
                  src_base + (size_t)row * stride + koff + c16 * 8);
        }
        asm volatile("cp.async.commit_group;" ::: "memory");
    };

    issueW(0, 0);

    for (int s = 0; s < T_STEPS; s++) {
        float acc[8][4];
#pragma unroll
        for (int nb = 0; nb < 8; nb++)
#pragma unroll
            for (int q = 0; q < 4; q++) acc[nb][q] = 0.0f;

        issueW(s, 1);

        for (int j = 0; j < CHUNKS; j++) {
            if (j + 2 < CHUNKS) {
                issueW(s, j + 2);
                asm volatile("cp.async.wait_group 2;" ::: "memory");
            } else if (j + 1 < CHUNKS) {
                asm volatile("cp.async.wait_group 1;" ::: "memory");
            } else {
                asm volatile("cp.async.wait_group 0;" ::: "memory");
            }
            __syncwarp();

            uint32_t Abase = abuf0 + (j % NSTAGE_A) * ABUF_BYTES;
            uint32_t Bbase = sb + j * 8192;
#pragma unroll
            for (int ks = 0; ks < 4; ks++) {
                uint32_t a0[4];
                ldsm4(a0, Abase + swz((wid * 16 + lrow) * 128 + ks * 32 + lcol));
#pragma unroll
                for (int nb4 = 0; nb4 < 4; nb4++) {
                    uint32_t b[4];
                    ldsm4(b, Bbase + swz((nb4 * 16 + lrow) * 128 + ks * 32 + lcol));
                    mma16816(acc[nb4 * 2 + 0], a0, b[0], b[2]);
                    mma16816(acc[nb4 * 2 + 1], a0, b[1], b[3]);
                }
            }
        }

        if (s + 1 < T_STEPS) issueW(s + 1, 0);

        float* sH = (float*)(sm + SMEM_SH);
#pragma unroll
        for (int rh = 0; rh < 2; rh++) {
            int row = wid * 16 + (lane >> 2) + rh * 8;
#pragma unroll
            for (int p = 0; p < 2; p++) {
#pragma unroll
                for (int t = 0; t < 2; t++) {
                    int q = rh * 2 + t;
                    int e = (rh * 2 + p) * 2 + t;
                    float iv = acc[0 + p][q] + bv[0 + p * 2 + t];
                    float fv = acc[2 + p][q] + bv[4 + p * 2 + t];
                    float gv = acc[4 + p][q] + bv[8 + p * 2 + t];
                    float ov = acc[6 + p][q] + bv[12 + p * 2 + t];
                    iv = sgm(iv);
                    fv = sgm(fv);
                    ov = sgm(ov);
                    gv = tanh_fast(gv);
                    float c = fv * cv[e] + iv * gv;
                    cv[e] = c;
                    sH[row * 17 + p * 8 + 2 * (lane & 3) + t] = ov * tanh_fast(c);
                }
            }
        }
        __syncwarp();

        {
            const int r = tid >> 1, half = tid & 1;
            const int m = mT * 256 + r;
            __half hi[8];
            float hv[8];
#pragma unroll
            for (int i = 0; i < 8; i++) {
                hv[i] = sH[r * 17 + half * 8 + i];
                hi[i] = __float2half(hv[i]);
            }
            __half* Aout = &g_Ah[(s + 1) & 1][0][0];
            *((uint4*)&Aout[(size_t)m * 512 + nT * 16 + half * 8]) = ((uint4*)hi)[0];
            if (s == T_STEPS - 1) {
                float4* pf = (float4*)&g_hfinal[(size_t)m * H_DIM + nT * 16 + half * 8];
                float4 t4;
                t4.x = hv[0]; t4.y = hv[1]; t4.z = hv[2]; t4.w = hv[3];
                pf[0] = t4;
                t4.x = hv[4]; t4.y = hv[5]; t4.z = hv[6]; t4.w = hv[7];
                pf[1] = t4;
            }
        }

        if (s + 1 < T_STEPS) {
            __threadfence();
            __syncthreads();
            if (tid == 0) {
                atomicAdd(bar, 1u);
                unsigned target = (unsigned)(s + 1) * MTGRP;
                unsigned v;
                do {
                    asm volatile("ld.acquire.gpu.u32 %0, [%1];"
                                 : "=r"(v) : "l"(bar));
                } while (v < target);
            }
            __syncthreads();
        }
    }
}

// ---------------- mlp1 via fp16 mma: z1 = tanh(h @ w1^T + b1) ----------------
// grid (9 nT, 8 mT, 2 head), 256 threads; CTA tile M=128 x N=64; K=512, 8 chunks
__global__ void __launch_bounds__(256) mlp1_mma_kernel(
    const float* __restrict__ lb1, const float* __restrict__ vb1)
{
    __shared__ char sm1[49152];          // 2 x (A 16KB + B 8KB)
    uint32_t sb = smem_u32(sm1);

    const int tid = threadIdx.x;
    const int wid = tid >> 5, lane = tid & 31;
    const int nT = blockIdx.x, mT = blockIdx.y, head = blockIdx.z;
    const float* __restrict__ b1 = head ? vb1 : lb1;
    const __half* __restrict__ Ah = &g_Ah[0][mT * 128][0];     // final h fp16
    const __half* __restrict__ W1 = &g_W1[head][nT * 64][0];
    float* __restrict__ z1 = g_z1[head];

    auto issue = [&](int j) {
        uint32_t base = sb + (j & 1) * 24576;
#pragma unroll
        for (int o = 0; o < 4; o++) {    // A: 128 rows x 128B
            int lin = o * 256 + tid;
            int row = lin >> 3, c16 = lin & 7;
            cpa16(base + swz(row * 128 + c16 * 16),
                  Ah + (size_t)row * 512 + j * 64 + c16 * 8);
        }
#pragma unroll
        for (int o = 0; o < 2; o++) {    // B: 64 rows x 128B
            int lin = o * 256 + tid;
            int row = lin >> 3, c16 = lin & 7;
            cpa16(base + 16384 + swz(row * 128 + c16 * 16),
                  W1 + (size_t)row * 512 + j * 64 + c16 * 8);
        }
        asm volatile("cp.async.commit_group;" ::: "memory");
    };

    float acc[8][4];
#pragma unroll
    for (int nb = 0; nb < 8; nb++)
#pragma unroll
        for (int q = 0; q < 4; q++) acc[nb][q] = 0.0f;

    const int lrow = lane & 15;
    const uint32_t lcol = (lane >> 4) * 16;

    issue(0);
    for (int j = 0; j < 8; j++) {
        if (j + 1 < 8) {
            issue(j + 1);
            asm volatile("cp.async.wait_group 1;" ::: "memory");
        } else {
            asm volatile("cp.async.wait_group 0;" ::: "memory");
        }
        __syncthreads();
        uint32_t Abase = sb + (j & 1) * 24576;
        uint32_t Bbase = Abase + 16384;
#pragma unroll
        for (int ks = 0; ks < 4; ks++) {
            uint32_t a0[4];
            ldsm4(a0, Abase + swz((wid * 16 + lrow) * 128 + ks * 32 + lcol));
#pragma unroll
            for (int nb4 = 0; nb4 < 4; nb4++) {
                uint32_t b[4];
                ldsm4(b, Bbase + swz((nb4 * 16 + lrow) * 128 + ks * 32 + lcol));
                mma16816(acc[nb4 * 2 + 0], a0, b[0], b[2]);
                mma16816(acc[nb4 * 2 + 1], a0, b[1], b[3]);
            }
        }
        __syncthreads();
    }

    // epilogue: bias + tanh, store z1 (n < 513 only)
#pragma unroll
    for (int nb = 0; nb < 8; nb++) {
        int n = nT * 64 + nb * 8 + 2 * (lane & 3);
#pragma unroll
        for (int t = 0; t < 2; t++) {
            if (n + t < H1) {
                float bvv = b1[n + t];
#pragma unroll
                for (int rh = 0; rh < 2; rh++) {
                    int row = mT * 128 + wid * 16 + (lane >> 2) + rh * 8;
                    z1[row * H1 + n + t] = tanh_fast(acc[nb][rh * 2 + t] + bvv);
                }
            }
        }
    }
}

// ---------------- mlp2 (fp32 SIMT) ----------------
__global__ __launch_bounds__(256) void mlp2_kernel(
    const float* __restrict__ lw2, const float* __restrict__ lb2,
    const float* __restrict__ vw2, const float* __restrict__ vb2,
    float* __restrict__ out)
{
    __shared__ float z1s[32 * 65];
    __shared__ float w2s[32 * 65];
    const int head = blockIdx.y;
    const float* __restrict__ w2 = head ? vw2 : lw2;
    const float* __restrict__ b2 = head ? vb2 : lb2;
    const float* __restrict__ z1 = g_z1[head];
    const int r0 = blockIdx.x * 32;
    const int tid = threadIdx.x, o = tid & 31, rg = tid >> 5;
    float acc[4] = {0.f, 0.f, 0.f, 0.f};
    for (int k0 = 0; k0 < H1; k0 += 64) {
#pragma unroll
        for (int i = 0; i < 8; i++) {
            int lin = tid + i * 256;
            int kk = lin & 63, rr = lin >> 6;
            int k = k0 + kk;
            z1s[rr * 65 + kk] = (k < H1) ? z1[(r0 + rr) * H1 + k] : 0.0f;
            w2s[rr * 65 + kk] = (k < H1) ? w2[rr * H1 + k] : 0.0f;
        }
        __syncthreads();
#pragma unroll
        for (int kk = 0; kk < 64; kk++) {
            float wv = w2s[o * 65 + kk];
#pragma unroll
            for (int r = 0; r < 4; r++) acc[r] += z1s[(rg * 4 + r) * 65 + kk] * wv;
        }
        __syncthreads();
    }
    float bvv = b2[o];
#pragma unroll
    for (int r = 0; r < 4; r++)
        out[(size_t)head * BATCH * OUT_DIM + (r0 + rg * 4 + r) * OUT_DIM + o] = tanhf(acc[r] + bvv);
}

// ---------------- launch ----------------
extern "C" void kernel_launch(void* const* d_in, const int* in_sizes, int n_in,
                              void* d_out, int out_size) {
    const float* x    = (const float*)d_in[0];
    const float* a    = (const float*)d_in[1];
    const float* m    = (const float*)d_in[2];
    const float* w_ih = (const float*)d_in[3];
    const float* w_hh = (const float*)d_in[4];
    const float* b_ih = (const float*)d_in[5];
    const float* b_hh = (const float*)d_in[6];
    const float* lw1  = (const float*)d_in[7];
    const float* lb1  = (const float*)d_in[8];
    const float* lw2  = (const float*)d_in[9];
    const float* lb2  = (const float*)d_in[10];
    const float* vw1  = (const float*)d_in[11];
    const float* vb1  = (const float*)d_in[12];
    const float* vw2  = (const float*)d_in[13];
    const float* vb2  = (const float*)d_in[14];

    cudaFuncSetAttribute(lstm_persistent_kernel,
                         cudaFuncAttributeMaxDynamicSharedMemorySize, SMEM_REQ);

    zero_kernel<<<512, 256>>>();
    maxm_kernel<<<200, 256>>>(m);
    prep_w_kernel<<<2048, 256>>>(w_ih, w_hh, b_ih, b_hh);
    prep_w1_kernel<<<dim3(576, 2), 256>>>(lw1, vw1);
    prep_x_kernel<<<dim3(T_STEPS, 16), 256>>>(x, a);

    lstm_persistent_kernel<<<NCTA, 512, SMEM_REQ>>>();

    mlp1_mma_kernel<<<dim3(9, 8, 2), 256>>>(lb1, vb1);
    mlp2_kernel<<<dim3(32, 2), 256>>>(lw2, lb2, vw2, vb2, (float*)d_out);
}